// round 14
// baseline (speedup 1.0000x reference)
#include <cuda_runtime.h>
#include <cuda_bf16.h>
#include <math.h>
#include <cstdint>
#include <cstddef>

#define B_   8
#define N_   2048
#define F_   256
#define ALPHA 0.2f

// ---------------- device scratch (allocation-free rule) ----------------
__device__ float g_s1[B_ * N_];
__device__ float g_s2[B_ * N_];
__device__ __nv_bfloat16 g_WhT_hi[B_ * F_ * N_];   // [b][f][j]
__device__ __nv_bfloat16 g_WhT_lo[B_ * F_ * N_];
__device__ __nv_bfloat16 gW_hi[F_ * F_];           // W split, [out][k]
__device__ __nv_bfloat16 gW_lo[F_ * F_];

__device__ __forceinline__ uint32_t smem_u32(const void* p) {
    uint32_t a;
    asm("{ .reg .u64 t; cvta.to.shared.u64 t, %1; cvt.u32.u64 %0, t; }"
        : "=r"(a) : "l"(p));
    return a;
}
__device__ __forceinline__ void ldm_x4(uint32_t& r0, uint32_t& r1,
                                       uint32_t& r2, uint32_t& r3, uint32_t addr) {
    asm volatile("ldmatrix.sync.aligned.m8n8.x4.shared.b16 {%0,%1,%2,%3}, [%4];"
                 : "=r"(r0), "=r"(r1), "=r"(r2), "=r"(r3) : "r"(addr));
}
__device__ __forceinline__ void mma_bf16(float* d, const uint32_t* a,
                                         uint32_t b0, uint32_t b1) {
    asm volatile(
        "mma.sync.aligned.m16n8k16.row.col.f32.bf16.bf16.f32 "
        "{%0,%1,%2,%3}, {%4,%5,%6,%7}, {%8,%9}, {%0,%1,%2,%3};"
        : "+f"(d[0]), "+f"(d[1]), "+f"(d[2]), "+f"(d[3])
        : "r"(a[0]), "r"(a[1]), "r"(a[2]), "r"(a[3]), "r"(b0), "r"(b1));
}
__device__ __forceinline__ void cp_async16(uint32_t dst, const void* src) {
    asm volatile("cp.async.cg.shared.global [%0], [%1], 16;"
                 :: "r"(dst), "l"(src) : "memory");
}
#define CP_COMMIT() asm volatile("cp.async.commit_group;" ::: "memory")
#define CP_WAIT0()  asm volatile("cp.async.wait_group 0;" ::: "memory")

__device__ __forceinline__ void split_pair(float v0, float v1,
                                           uint32_t& hiP, uint32_t& loP) {
    __nv_bfloat16 h0 = __float2bfloat16(v0), h1 = __float2bfloat16(v1);
    float r0 = v0 - __bfloat162float(h0);
    float r1 = v1 - __bfloat162float(h1);
    __nv_bfloat16 l0 = __float2bfloat16(r0), l1 = __float2bfloat16(r1);
    __nv_bfloat162 hp = __halves2bfloat162(h0, h1);
    __nv_bfloat162 lp = __halves2bfloat162(l0, l1);
    hiP = *(uint32_t*)&hp;
    loP = *(uint32_t*)&lp;
}

// w-pair: leaky+exp+mask, bf16 hi/lo split, rowsum accumulate
__device__ __forceinline__ void make_w_pair(float s1v, int a0, int a1,
                                            float s20, float s21,
                                            float& lsum, uint32_t& hiP, uint32_t& loP)
{
    float x0 = s1v + s20; x0 = fmaxf(x0, ALPHA * x0);
    float x1 = s1v + s21; x1 = fmaxf(x1, ALPHA * x1);
    float w0 = (a0 > 0) ? __expf(x0) : 0.f;
    float w1 = (a1 > 0) ? __expf(x1) : 0.f;
    lsum += w0 + w1;
    split_pair(w0, w1, hiP, loP);
}

// ---------------------------------------------------------------------------
// Kernel 0: split W (256x256 fp32, [out][k]) into bf16 hi/lo.
// ---------------------------------------------------------------------------
__global__ void __launch_bounds__(256) k0_convW(const float* __restrict__ Ww)
{
    int idx = (blockIdx.x * 256 + threadIdx.x) * 2;
    float2 v = *(const float2*)(Ww + idx);
    uint32_t hw, lw;
    split_pair(v.x, v.y, hw, lw);
    *(uint32_t*)(gW_hi + idx) = hw;
    *(uint32_t*)(gW_lo + idx) = lw;
}

// ---------------------------------------------------------------------------
// k1 tile constants (R12-proven)
// ---------------------------------------------------------------------------
#define KC2   32
#define AST   40
#define BST   40
#define A_BYTES (128 * AST * 2)           // 10240
#define B_BYTES (256 * BST * 2)           // 20480
#define STAGE   (2 * A_BYTES + 2 * B_BYTES)   // 61440
#define DYN_SMEM (2 * STAGE)                  // 122880

// k2 tile constants (KC=64, stride 72)
#define KC3   64
#define NCH3  (N_ / KC3)                  // 32 chunks
#define ST3   72
#define A3_BYTES (128 * ST3 * 2)          // 18432
#define B3_BYTES (256 * ST3 * 2)          // 36864
#define STAGE3  (2 * A3_BYTES + 2 * B3_BYTES) // 110592
#define DYN_SMEM3 (2 * STAGE3)                // 221184

// ---------------------------------------------------------------------------
// Kernel 1: HMMA Wh = h @ W^T (+bias, s1/s2), bf16 3-term split. (R12 version)
// ---------------------------------------------------------------------------
__global__ void __launch_bounds__(512, 1) k1_hmma(
    const float* __restrict__ h,  const float* __restrict__ Wb,
    const float* __restrict__ aiw, const float* __restrict__ aib,
    const float* __restrict__ ajw, const float* __restrict__ ajb)
{
    extern __shared__ __align__(16) char smRaw[];
    __shared__ float sWb[F_], sAi[F_], sAj[F_];
    __shared__ float red1[128][4], red2[128][4];

    const int t    = threadIdx.x;
    const int lane = t & 31;
    const int wid  = t >> 5;
    const int wm   = wid & 3;
    const int wn   = wid >> 2;
    const int row0 = blockIdx.x * 128;

    const uint32_t smBase = smem_u32(smRaw);

    if (t < F_) { sWb[t] = Wb[t]; sAi[t] = aiw[t]; sAj[t] = ajw[t]; }

    const int ig = t >> 2;
    const int jg = (t & 3) * 8;
    const int fB = t >> 1;
    const int hB = (t & 1) * 16;

    const float* hP = h + (size_t)(row0 + ig) * F_;
    const __nv_bfloat16* wHiP = gW_hi + fB * F_;
    const __nv_bfloat16* wLoP = gW_lo + fB * F_;

    float acc[2][8][4];
#pragma unroll
    for (int m = 0; m < 2; m++)
#pragma unroll
        for (int n = 0; n < 8; n++)
#pragma unroll
            for (int q = 0; q < 4; q++) acc[m][n][q] = 0.f;

    uint32_t hw[4], lw[4];

    {
        float4 v0 = *(const float4*)(hP + jg);
        float4 v1 = *(const float4*)(hP + jg + 4);
        split_pair(v0.x, v0.y, hw[0], lw[0]);
        split_pair(v0.z, v0.w, hw[1], lw[1]);
        split_pair(v1.x, v1.y, hw[2], lw[2]);
        split_pair(v1.z, v1.w, hw[3], lw[3]);

        uint32_t dH = smBase + 2 * A_BYTES + (uint32_t)(fB * BST + hB) * 2u;
        cp_async16(dH,      wHiP + hB);
        cp_async16(dH + 16, wHiP + hB + 8);
        cp_async16(dH + B_BYTES,      wLoP + hB);
        cp_async16(dH + B_BYTES + 16, wLoP + hB + 8);
        CP_COMMIT();

        uint32_t off = (uint32_t)(ig * AST + jg) * 2u;
        asm volatile("st.shared.v4.b32 [%0], {%1,%2,%3,%4};"
                     :: "r"(smBase + off), "r"(hw[0]), "r"(hw[1]), "r"(hw[2]), "r"(hw[3]));
        asm volatile("st.shared.v4.b32 [%0], {%1,%2,%3,%4};"
                     :: "r"(smBase + A_BYTES + off), "r"(lw[0]), "r"(lw[1]), "r"(lw[2]), "r"(lw[3]));
        CP_WAIT0();
    }
    __syncthreads();

    for (int c = 0; c < 8; ++c) {
        const uint32_t sb   = smBase + (c & 1) * STAGE;
        const uint32_t sbN  = smBase + ((c + 1) & 1) * STAGE;
        const uint32_t aHiS = sb;
        const uint32_t aLoS = sb + A_BYTES;
        const uint32_t bHiS = sb + 2 * A_BYTES;
        const uint32_t bLoS = bHiS + B_BYTES;
        const bool doNext = (c + 1 < 8);
        const int  kn = (c + 1) * KC2;

        float4 ph0, ph1;
        if (doNext) {
            uint32_t dH = sbN + 2 * A_BYTES + (uint32_t)(fB * BST + hB) * 2u;
            cp_async16(dH,      wHiP + kn + hB);
            cp_async16(dH + 16, wHiP + kn + hB + 8);
            cp_async16(dH + B_BYTES,      wLoP + kn + hB);
            cp_async16(dH + B_BYTES + 16, wLoP + kn + hB + 8);
            CP_COMMIT();
            ph0 = *(const float4*)(hP + kn + jg);
            ph1 = *(const float4*)(hP + kn + jg + 4);
        }

#pragma unroll
        for (int ks = 0; ks < 2; ++ks) {
            const int k0 = ks * 16;
            uint32_t ah[2][4], al[2][4];
#pragma unroll
            for (int mt = 0; mt < 2; ++mt) {
                int arow = wm * 32 + mt * 16 + (lane & 15);
                uint32_t aoff = (uint32_t)(arow * AST + k0 + ((lane >> 4) << 3)) * 2u;
                ldm_x4(ah[mt][0], ah[mt][1], ah[mt][2], ah[mt][3], aHiS + aoff);
                ldm_x4(al[mt][0], al[mt][1], al[mt][2], al[mt][3], aLoS + aoff);
            }
#pragma unroll
            for (int pr = 0; pr < 4; ++pr) {
                int n0   = wn * 64 + pr * 16;
                int rowB = n0 + (lane & 7) + ((lane >> 4) << 3);
                int colB = k0 + (((lane >> 3) & 1) << 3);
                uint32_t boff = (uint32_t)(rowB * BST + colB) * 2u;
                uint32_t bh0, bh1, bh2, bh3, bl0, bl1, bl2, bl3;
                ldm_x4(bh0, bh1, bh2, bh3, bHiS + boff);
                ldm_x4(bl0, bl1, bl2, bl3, bLoS + boff);
                mma_bf16(acc[0][pr * 2],     ah[0], bh0, bh1);
                mma_bf16(acc[1][pr * 2],     ah[1], bh0, bh1);
                mma_bf16(acc[0][pr * 2 + 1], ah[0], bh2, bh3);
                mma_bf16(acc[1][pr * 2 + 1], ah[1], bh2, bh3);
                mma_bf16(acc[0][pr * 2],     ah[0], bl0, bl1);
                mma_bf16(acc[1][pr * 2],     ah[1], bl0, bl1);
                mma_bf16(acc[0][pr * 2 + 1], ah[0], bl2, bl3);
                mma_bf16(acc[1][pr * 2 + 1], ah[1], bl2, bl3);
                mma_bf16(acc[0][pr * 2],     al[0], bh0, bh1);
                mma_bf16(acc[1][pr * 2],     al[1], bh0, bh1);
                mma_bf16(acc[0][pr * 2 + 1], al[0], bh2, bh3);
                mma_bf16(acc[1][pr * 2 + 1], al[1], bh2, bh3);
            }
        }

        if (doNext) {
            split_pair(ph0.x, ph0.y, hw[0], lw[0]);
            split_pair(ph0.z, ph0.w, hw[1], lw[1]);
            split_pair(ph1.x, ph1.y, hw[2], lw[2]);
            split_pair(ph1.z, ph1.w, hw[3], lw[3]);
            uint32_t off = (uint32_t)(ig * AST + jg) * 2u;
            asm volatile("st.shared.v4.b32 [%0], {%1,%2,%3,%4};"
                         :: "r"(sbN + off), "r"(hw[0]), "r"(hw[1]), "r"(hw[2]), "r"(hw[3]));
            asm volatile("st.shared.v4.b32 [%0], {%1,%2,%3,%4};"
                         :: "r"(sbN + A_BYTES + off), "r"(lw[0]), "r"(lw[1]), "r"(lw[2]), "r"(lw[3]));
            CP_WAIT0();
        }
        __syncthreads();
    }

    // ---- epilogue part 1: bias, s1/s2 reduction ----
    const int g  = lane >> 2;
    const int tq = lane & 3;
#pragma unroll
    for (int mt = 0; mt < 2; ++mt) {
        int r0l = wm * 32 + mt * 16 + g;
        int r1l = r0l + 8;
        float a1_0 = 0.f, a2_0 = 0.f, a1_1 = 0.f, a2_1 = 0.f;
#pragma unroll
        for (int nt = 0; nt < 8; ++nt) {
            int col = wn * 64 + nt * 8 + 2 * tq;
            float b0 = sWb[col], b1 = sWb[col + 1];
            float i0v = sAi[col], i1v = sAi[col + 1];
            float j0v = sAj[col], j1v = sAj[col + 1];
            acc[mt][nt][0] += b0; acc[mt][nt][1] += b1;
            acc[mt][nt][2] += b0; acc[mt][nt][3] += b1;
            a1_0 = fmaf(acc[mt][nt][0], i0v, fmaf(acc[mt][nt][1], i1v, a1_0));
            a2_0 = fmaf(acc[mt][nt][0], j0v, fmaf(acc[mt][nt][1], j1v, a2_0));
            a1_1 = fmaf(acc[mt][nt][2], i0v, fmaf(acc[mt][nt][3], i1v, a1_1));
            a2_1 = fmaf(acc[mt][nt][2], j0v, fmaf(acc[mt][nt][3], j1v, a2_1));
        }
#pragma unroll
        for (int off = 1; off <= 2; off <<= 1) {
            a1_0 += __shfl_xor_sync(0xffffffffu, a1_0, off);
            a2_0 += __shfl_xor_sync(0xffffffffu, a2_0, off);
            a1_1 += __shfl_xor_sync(0xffffffffu, a1_1, off);
            a2_1 += __shfl_xor_sync(0xffffffffu, a2_1, off);
        }
        if (tq == 0) {
            red1[r0l][wn] = a1_0; red2[r0l][wn] = a2_0;
            red1[r1l][wn] = a1_1; red2[r1l][wn] = a2_1;
        }
    }
    __syncthreads();
    if (t < 128) {
        g_s1[row0 + t] = red1[t][0] + red1[t][1] + red1[t][2] + red1[t][3] + aib[0];
        g_s2[row0 + t] = red2[t][0] + red2[t][1] + red2[t][2] + red2[t][3] + ajb[0];
    }

    // ---- epilogue part 2: FUSED transpose + bf16 split, two 128f passes ----
    float* ts = (float*)smRaw;
    const int b   = row0 >> 11;
    const int jlo = row0 & (N_ - 1);
    const int fLoc = t >> 2;
    const int jseg = (t & 3) * 32;

#pragma unroll
    for (int fh = 0; fh < 2; ++fh) {
        __syncthreads();
        if ((wn >> 1) == fh) {
#pragma unroll
            for (int mt = 0; mt < 2; ++mt) {
                int r0l = wm * 32 + mt * 16 + g;
                int r1l = r0l + 8;
#pragma unroll
                for (int nt = 0; nt < 8; ++nt) {
                    int colL = (wn & 1) * 64 + nt * 8 + 2 * tq;
                    *(float2*)&ts[r0l * 132 + colL] =
                        make_float2(acc[mt][nt][0], acc[mt][nt][1]);
                    *(float2*)&ts[r1l * 132 + colL] =
                        make_float2(acc[mt][nt][2], acc[mt][nt][3]);
                }
            }
        }
        __syncthreads();
        uint32_t hp[16], lp[16];
#pragma unroll
        for (int e = 0; e < 32; e += 2) {
            float v0 = ts[(jseg + e) * 132 + fLoc];
            float v1 = ts[(jseg + e + 1) * 132 + fLoc];
            split_pair(v0, v1, hp[e >> 1], lp[e >> 1]);
        }
        size_t dst = ((size_t)(b * F_ + fh * 128 + fLoc)) * N_ + jlo + jseg;
        uint4* dh = (uint4*)(g_WhT_hi + dst);
        uint4* dl = (uint4*)(g_WhT_lo + dst);
        dh[0] = make_uint4(hp[0],  hp[1],  hp[2],  hp[3]);
        dh[1] = make_uint4(hp[4],  hp[5],  hp[6],  hp[7]);
        dh[2] = make_uint4(hp[8],  hp[9],  hp[10], hp[11]);
        dh[3] = make_uint4(hp[12], hp[13], hp[14], hp[15]);
        dl[0] = make_uint4(lp[0],  lp[1],  lp[2],  lp[3]);
        dl[1] = make_uint4(lp[4],  lp[5],  lp[6],  lp[7]);
        dl[2] = make_uint4(lp[8],  lp[9],  lp[10], lp[11]);
        dl[3] = make_uint4(lp[12], lp[13], lp[14], lp[15]);
    }
}

// ---------------------------------------------------------------------------
// Kernel 2: HMMA attention GEMM. KC=64 (32 chunks, half the syncs).
//   512 thr, 128i x 256f. Next-chunk w computed AND stored immediately in two
//   groups (ks==2 / ks==3) so register footprint stays flat.
// ---------------------------------------------------------------------------
__global__ void __launch_bounds__(512, 1) k2_attn(
    const int* __restrict__ adj, float* __restrict__ out)
{
    extern __shared__ __align__(16) char smRaw[];
    __shared__ float s1S[128];
    __shared__ __align__(16) float s2S[N_];   // reused as rowsum scratch post-loop

    const int t    = threadIdx.x;
    const int lane = t & 31;
    const int wid  = t >> 5;
    const int wm   = wid & 3;
    const int wn   = wid >> 2;
    const int b    = blockIdx.x >> 4;
    const int i0   = (blockIdx.x & 15) * 128;

    const uint32_t smBase = smem_u32(smRaw);

    if (t < 128) s1S[t] = g_s1[b * N_ + i0 + t];
    {
        const float4* s2g = (const float4*)(g_s2 + b * N_);
#pragma unroll
        for (int k = t; k < N_ / 4; k += 512) ((float4*)s2S)[k] = s2g[k];
    }

    const int ig = t >> 2;                 // A row 0..127
    const int jg = (t & 3) * 16;           // 16-j subgroup
    const int fB = t >> 1;                 // B row 0..255
    const int hB = (t & 1) * 32;           // 32-j half (64B)

    const int* adjP = adj + (size_t)(b * N_ + i0 + ig) * N_;
    const __nv_bfloat16* bhP = g_WhT_hi + (size_t)(b * F_ + fB) * N_;
    const __nv_bfloat16* blP = g_WhT_lo + (size_t)(b * F_ + fB) * N_;

    float acc[2][8][4];
#pragma unroll
    for (int m = 0; m < 2; m++)
#pragma unroll
        for (int n = 0; n < 8; n++)
#pragma unroll
            for (int q = 0; q < 4; q++) acc[m][n][q] = 0.f;
    float lsum = 0.f;

    uint32_t hw[4], lw[4];

    __syncthreads();   // s1S/s2S visible

    // ---- prologue: chunk 0 (B cp.async + 16 w values in two groups) ----
    {
        uint32_t dH = smBase + 2 * A3_BYTES + (uint32_t)(fB * ST3 + hB) * 2u;
        cp_async16(dH,      bhP + hB);
        cp_async16(dH + 16, bhP + hB + 8);
        cp_async16(dH + 32, bhP + hB + 16);
        cp_async16(dH + 48, bhP + hB + 24);
        uint32_t dL = dH + B3_BYTES;
        cp_async16(dL,      blP + hB);
        cp_async16(dL + 16, blP + hB + 8);
        cp_async16(dL + 32, blP + hB + 16);
        cp_async16(dL + 48, blP + hB + 24);
        CP_COMMIT();

        const float s1v = s1S[ig];
        int4 a0 = *(const int4*)(adjP + jg);
        int4 a1 = *(const int4*)(adjP + jg + 4);
        make_w_pair(s1v, a0.x, a0.y, s2S[jg + 0], s2S[jg + 1], lsum, hw[0], lw[0]);
        make_w_pair(s1v, a0.z, a0.w, s2S[jg + 2], s2S[jg + 3], lsum, hw[1], lw[1]);
        make_w_pair(s1v, a1.x, a1.y, s2S[jg + 4], s2S[jg + 5], lsum, hw[2], lw[2]);
        make_w_pair(s1v, a1.z, a1.w, s2S[jg + 6], s2S[jg + 7], lsum, hw[3], lw[3]);
        uint32_t off = (uint32_t)(ig * ST3 + jg) * 2u;
        asm volatile("st.shared.v4.b32 [%0], {%1,%2,%3,%4};"
                     :: "r"(smBase + off), "r"(hw[0]), "r"(hw[1]), "r"(hw[2]), "r"(hw[3]));
        asm volatile("st.shared.v4.b32 [%0], {%1,%2,%3,%4};"
                     :: "r"(smBase + A3_BYTES + off), "r"(lw[0]), "r"(lw[1]), "r"(lw[2]), "r"(lw[3]));

        int4 a2 = *(const int4*)(adjP + jg + 8);
        int4 a3 = *(const int4*)(adjP + jg + 12);
        make_w_pair(s1v, a2.x, a2.y, s2S[jg + 8],  s2S[jg + 9],  lsum, hw[0], lw[0]);
        make_w_pair(s1v, a2.z, a2.w, s2S[jg + 10], s2S[jg + 11], lsum, hw[1], lw[1]);
        make_w_pair(s1v, a3.x, a3.y, s2S[jg + 12], s2S[jg + 13], lsum, hw[2], lw[2]);
        make_w_pair(s1v, a3.z, a3.w, s2S[jg + 14], s2S[jg + 15], lsum, hw[3], lw[3]);
        asm volatile("st.shared.v4.b32 [%0], {%1,%2,%3,%4};"
                     :: "r"(smBase + off + 16), "r"(hw[0]), "r"(hw[1]), "r"(hw[2]), "r"(hw[3]));
        asm volatile("st.shared.v4.b32 [%0], {%1,%2,%3,%4};"
                     :: "r"(smBase + A3_BYTES + off + 16), "r"(lw[0]), "r"(lw[1]), "r"(lw[2]), "r"(lw[3]));
        CP_WAIT0();
    }
    __syncthreads();

    for (int c = 0; c < NCH3; ++c) {
        const uint32_t sb   = smBase + (c & 1) * STAGE3;
        const uint32_t sbN  = smBase + ((c + 1) & 1) * STAGE3;
        const uint32_t aHiS = sb;
        const uint32_t aLoS = sb + A3_BYTES;
        const uint32_t bHiS = sb + 2 * A3_BYTES;
        const uint32_t bLoS = bHiS + B3_BYTES;
        const bool doNext = (c + 1 < NCH3);
        const int  jn = (c + 1) * KC3;

        int4 pA0, pA1, pA2, pA3;
        if (doNext) {
            uint32_t dH = sbN + 2 * A3_BYTES + (uint32_t)(fB * ST3 + hB) * 2u;
            cp_async16(dH,      bhP + jn + hB);
            cp_async16(dH + 16, bhP + jn + hB + 8);
            cp_async16(dH + 32, bhP + jn + hB + 16);
            cp_async16(dH + 48, bhP + jn + hB + 24);
            uint32_t dL = dH + B3_BYTES;
            cp_async16(dL,      blP + jn + hB);
            cp_async16(dL + 16, blP + jn + hB + 8);
            cp_async16(dL + 32, blP + jn + hB + 16);
            cp_async16(dL + 48, blP + jn + hB + 24);
            CP_COMMIT();
            pA0 = *(const int4*)(adjP + jn + jg);
            pA1 = *(const int4*)(adjP + jn + jg + 4);
        }
        const float s1v = s1S[ig];
        const uint32_t aOffN = (uint32_t)(ig * ST3 + jg) * 2u;

#pragma unroll
        for (int ks = 0; ks < 4; ++ks) {
            const int k0 = ks * 16;
            uint32_t ah[2][4], al[2][4];
#pragma unroll
            for (int mt = 0; mt < 2; ++mt) {
                int arow = wm * 32 + mt * 16 + (lane & 15);
                uint32_t aoff = (uint32_t)(arow * ST3 + k0 + ((lane >> 4) << 3)) * 2u;
                ldm_x4(ah[mt][0], ah[mt][1], ah[mt][2], ah[mt][3], aHiS + aoff);
                ldm_x4(al[mt][0], al[mt][1], al[mt][2], al[mt][3], aLoS + aoff);
            }
#pragma unroll
            for (int pr = 0; pr < 4; ++pr) {
                int n0   = wn * 64 + pr * 16;
                int rowB = n0 + (lane & 7) + ((lane >> 4) << 3);
                int colB = k0 + (((lane >> 3) & 1) << 3);
                uint32_t boff = (uint32_t)(rowB * ST3 + colB) * 2u;
                uint32_t bh0, bh1, bh2, bh3, bl0, bl1, bl2, bl3;
                ldm_x4(bh0, bh1, bh2, bh3, bHiS + boff);
                ldm_x4(bl0, bl1, bl2, bl3, bLoS + boff);
                mma_bf16(acc[0][pr * 2],     ah[0], bh0, bh1);
                mma_bf16(acc[1][pr * 2],     ah[1], bh0, bh1);
                mma_bf16(acc[0][pr * 2 + 1], ah[0], bh2, bh3);
                mma_bf16(acc[1][pr * 2 + 1], ah[1], bh2, bh3);
                mma_bf16(acc[0][pr * 2],     ah[0], bl0, bl1);
                mma_bf16(acc[1][pr * 2],     ah[1], bl0, bl1);
                mma_bf16(acc[0][pr * 2 + 1], ah[0], bl2, bl3);
                mma_bf16(acc[1][pr * 2 + 1], ah[1], bl2, bl3);
                mma_bf16(acc[0][pr * 2],     al[0], bh0, bh1);
                mma_bf16(acc[1][pr * 2],     al[1], bh0, bh1);
                mma_bf16(acc[0][pr * 2 + 1], al[0], bh2, bh3);
                mma_bf16(acc[1][pr * 2 + 1], al[1], bh2, bh3);

                if (doNext) {
                    if (ks == 1 && pr == 0) {
                        pA2 = *(const int4*)(adjP + jn + jg + 8);
                        pA3 = *(const int4*)(adjP + jn + jg + 12);
                    }
                    if (ks == 2) {
                        int a0 = (pr < 2) ? ((pr == 0) ? pA0.x : pA0.z)
                                          : ((pr == 2) ? pA1.x : pA1.z);
                        int a1 = (pr < 2) ? ((pr == 0) ? pA0.y : pA0.w)
                                          : ((pr == 2) ? pA1.y : pA1.w);
                        make_w_pair(s1v, a0, a1,
                                    s2S[jn + jg + 2 * pr], s2S[jn + jg + 2 * pr + 1],
                                    lsum, hw[pr], lw[pr]);
                        if (pr == 3) {
                            asm volatile("st.shared.v4.b32 [%0], {%1,%2,%3,%4};"
                                         :: "r"(sbN + aOffN), "r"(hw[0]), "r"(hw[1]), "r"(hw[2]), "r"(hw[3]));
                            asm volatile("st.shared.v4.b32 [%0], {%1,%2,%3,%4};"
                                         :: "r"(sbN + A3_BYTES + aOffN), "r"(lw[0]), "r"(lw[1]), "r"(lw[2]), "r"(lw[3]));
                        }
                    }
                    if (ks == 3) {
                        int a0 = (pr < 2) ? ((pr == 0) ? pA2.x : pA2.z)
                                          : ((pr == 2) ? pA3.x : pA3.z);
                        int a1 = (pr < 2) ? ((pr == 0) ? pA2.y : pA2.w)
                                          : ((pr == 2) ? pA3.y : pA3.w);
                        make_w_pair(s1v, a0, a1,
                                    s2S[jn + jg + 8 + 2 * pr], s2S[jn + jg + 9 + 2 * pr],
                                    lsum, hw[pr], lw[pr]);
                        if (pr == 3) {
                            asm volatile("st.shared.v4.b32 [%0], {%1,%2,%3,%4};"
                                         :: "r"(sbN + aOffN + 16), "r"(hw[0]), "r"(hw[1]), "r"(hw[2]), "r"(hw[3]));
                            asm volatile("st.shared.v4.b32 [%0], {%1,%2,%3,%4};"
                                         :: "r"(sbN + A3_BYTES + aOffN + 16), "r"(lw[0]), "r"(lw[1]), "r"(lw[2]), "r"(lw[3]));
                        }
                    }
                }
            }
        }

        if (doNext) CP_WAIT0();
        __syncthreads();
    }

    // ---- row-sum reduce (overlay scratch on s2S, dead after mainloop) ----
    s2S[ig * 4 + (t & 3)] = lsum;
    __syncthreads();
    float* rInv = s2S + 512;
    if (t < 128) rInv[t] = 1.f / (s2S[4 * t] + s2S[4 * t + 1] + s2S[4 * t + 2] + s2S[4 * t + 3]);
    __syncthreads();

    // ---- epilogue: normalize + ELU + store ----
    const int g  = lane >> 2;
    const int tq = lane & 3;
#pragma unroll
    for (int mt = 0; mt < 2; ++mt) {
        int r0l = wm * 32 + mt * 16 + g;
        int r1l = r0l + 8;
        float inv0 = rInv[r0l], inv1 = rInv[r1l];
        size_t o0 = ((size_t)(b * N_ + i0 + r0l)) * F_;
        size_t o1 = ((size_t)(b * N_ + i0 + r1l)) * F_;
#pragma unroll
        for (int nt = 0; nt < 8; ++nt) {
            int col = wn * 64 + nt * 8 + 2 * tq;
            float x0 = acc[mt][nt][0] * inv0;
            float x1 = acc[mt][nt][1] * inv0;
            float x2 = acc[mt][nt][2] * inv1;
            float x3 = acc[mt][nt][3] * inv1;
            x0 = (x0 > 0.f) ? x0 : expm1f(x0);
            x1 = (x1 > 0.f) ? x1 : expm1f(x1);
            x2 = (x2 > 0.f) ? x2 : expm1f(x2);
            x3 = (x3 > 0.f) ? x3 : expm1f(x3);
            *(float2*)(out + o0 + col) = make_float2(x0, x1);
            *(float2*)(out + o1 + col) = make_float2(x2, x3);
        }
    }
}

// ---------------------------------------------------------------------------
extern "C" void kernel_launch(void* const* d_in, const int* in_sizes, int n_in,
                              void* d_out, int out_size)
{
    const float* h   = (const float*)d_in[0];
    const int*   adj = (const int*)  d_in[1];
    const float* Ww  = (const float*)d_in[2];
    const float* Wb  = (const float*)d_in[3];
    const float* aiw = (const float*)d_in[4];
    const float* aib = (const float*)d_in[5];
    const float* ajw = (const float*)d_in[6];
    const float* ajb = (const float*)d_in[7];
    float* out = (float*)d_out;

    static bool attrDone = false;
    if (!attrDone) {
        cudaFuncSetAttribute(k1_hmma, cudaFuncAttributeMaxDynamicSharedMemorySize,
                             DYN_SMEM);
        cudaFuncSetAttribute(k2_attn, cudaFuncAttributeMaxDynamicSharedMemorySize,
                             DYN_SMEM3);
        attrDone = true;
    }

    k0_convW<<<128, 256>>>(Ww);
    k1_hmma<<<(B_ * N_) / 128, 512, DYN_SMEM>>>(h, Wb, aiw, aib, ajw, ajb);
    k2_attn<<<B_ * (N_ / 128), 512, DYN_SMEM3>>>(adj, out);
}

// round 15
// speedup vs baseline: 1.1206x; 1.1206x over previous
#include <cuda_runtime.h>
#include <cuda_bf16.h>
#include <math.h>
#include <cstdint>
#include <cstddef>

#define B_   8
#define N_   2048
#define F_   256
#define ALPHA 0.2f

// ---------------- device scratch (allocation-free rule) ----------------
__device__ float g_s1[B_ * N_];
__device__ float g_s2[B_ * N_];
__device__ __nv_bfloat16 g_WhT_hi[B_ * F_ * N_];   // [b][f][j]
__device__ __nv_bfloat16 g_WhT_lo[B_ * F_ * N_];
__device__ __nv_bfloat16 gW_hi[F_ * F_];           // W split, [out][k]
__device__ __nv_bfloat16 gW_lo[F_ * F_];

__device__ __forceinline__ uint32_t smem_u32(const void* p) {
    uint32_t a;
    asm("{ .reg .u64 t; cvta.to.shared.u64 t, %1; cvt.u32.u64 %0, t; }"
        : "=r"(a) : "l"(p));
    return a;
}
__device__ __forceinline__ void ldm_x4(uint32_t& r0, uint32_t& r1,
                                       uint32_t& r2, uint32_t& r3, uint32_t addr) {
    asm volatile("ldmatrix.sync.aligned.m8n8.x4.shared.b16 {%0,%1,%2,%3}, [%4];"
                 : "=r"(r0), "=r"(r1), "=r"(r2), "=r"(r3) : "r"(addr));
}
__device__ __forceinline__ void mma_bf16(float* d, const uint32_t* a,
                                         uint32_t b0, uint32_t b1) {
    asm volatile(
        "mma.sync.aligned.m16n8k16.row.col.f32.bf16.bf16.f32 "
        "{%0,%1,%2,%3}, {%4,%5,%6,%7}, {%8,%9}, {%0,%1,%2,%3};"
        : "+f"(d[0]), "+f"(d[1]), "+f"(d[2]), "+f"(d[3])
        : "r"(a[0]), "r"(a[1]), "r"(a[2]), "r"(a[3]), "r"(b0), "r"(b1));
}
__device__ __forceinline__ void cp_async16(uint32_t dst, const void* src) {
    asm volatile("cp.async.cg.shared.global [%0], [%1], 16;"
                 :: "r"(dst), "l"(src) : "memory");
}
#define CP_COMMIT() asm volatile("cp.async.commit_group;" ::: "memory")
#define CP_WAIT0()  asm volatile("cp.async.wait_group 0;" ::: "memory")

__device__ __forceinline__ void split_pair(float v0, float v1,
                                           uint32_t& hiP, uint32_t& loP) {
    __nv_bfloat16 h0 = __float2bfloat16(v0), h1 = __float2bfloat16(v1);
    float r0 = v0 - __bfloat162float(h0);
    float r1 = v1 - __bfloat162float(h1);
    __nv_bfloat16 l0 = __float2bfloat16(r0), l1 = __float2bfloat16(r1);
    __nv_bfloat162 hp = __halves2bfloat162(h0, h1);
    __nv_bfloat162 lp = __halves2bfloat162(l0, l1);
    hiP = *(uint32_t*)&hp;
    loP = *(uint32_t*)&lp;
}

// w-pair: leaky+exp+mask, bf16 hi/lo split, rowsum accumulate
__device__ __forceinline__ void make_w_pair(float s1v, int a0, int a1,
                                            float s20, float s21,
                                            float& lsum, uint32_t& hiP, uint32_t& loP)
{
    float x0 = s1v + s20; x0 = fmaxf(x0, ALPHA * x0);
    float x1 = s1v + s21; x1 = fmaxf(x1, ALPHA * x1);
    float w0 = (a0 > 0) ? __expf(x0) : 0.f;
    float w1 = (a1 > 0) ? __expf(x1) : 0.f;
    lsum += w0 + w1;
    split_pair(w0, w1, hiP, loP);
}

// ---------------------------------------------------------------------------
// Kernel 0: split W (256x256 fp32, [out][k]) into bf16 hi/lo.
// ---------------------------------------------------------------------------
__global__ void __launch_bounds__(256) k0_convW(const float* __restrict__ Ww)
{
    int idx = (blockIdx.x * 256 + threadIdx.x) * 2;
    float2 v = *(const float2*)(Ww + idx);
    uint32_t hw, lw;
    split_pair(v.x, v.y, hw, lw);
    *(uint32_t*)(gW_hi + idx) = hw;
    *(uint32_t*)(gW_lo + idx) = lw;
}

// ---------------------------------------------------------------------------
// Shared tile constants (k1_hmma and k2 use the same skeleton)
// ---------------------------------------------------------------------------
#define KC2   32
#define AST   40
#define BST   40
#define A_BYTES (128 * AST * 2)           // 10240
#define B_BYTES (256 * BST * 2)           // 20480
#define STAGE   (2 * A_BYTES + 2 * B_BYTES)   // 61440
#define DYN_SMEM (2 * STAGE)                  // 122880

// ---------------------------------------------------------------------------
// Kernel 1: HMMA Wh = h @ W^T (+bias, s1/s2), bf16 3-term split.
//   CTA 128 rows x 256 out, 512 thr, 8 k-chunks of 32.
//   FUSED epilogue: stages the output tile in smem (2 x 128f passes) and
//   writes WhT hi/lo directly (transpose+split) — no g_Wh round-trip.
// ---------------------------------------------------------------------------
__global__ void __launch_bounds__(512, 1) k1_hmma(
    const float* __restrict__ h,  const float* __restrict__ Wb,
    const float* __restrict__ aiw, const float* __restrict__ aib,
    const float* __restrict__ ajw, const float* __restrict__ ajb)
{
    extern __shared__ __align__(16) char smRaw[];
    __shared__ float sWb[F_], sAi[F_], sAj[F_];
    __shared__ float red1[128][4], red2[128][4];

    const int t    = threadIdx.x;
    const int lane = t & 31;
    const int wid  = t >> 5;
    const int wm   = wid & 3;
    const int wn   = wid >> 2;
    const int row0 = blockIdx.x * 128;

    const uint32_t smBase = smem_u32(smRaw);

    if (t < F_) { sWb[t] = Wb[t]; sAi[t] = aiw[t]; sAj[t] = ajw[t]; }

    // ---- roles (identical to k2) ----
    const int ig = t >> 2;                   // A row 0..127
    const int jg = (t & 3) * 8;              // 8-k subgroup
    const int fB = t >> 1;                   // B row (out) 0..255
    const int hB = (t & 1) * 16;

    const float* hP = h + (size_t)(row0 + ig) * F_;
    const __nv_bfloat16* wHiP = gW_hi + fB * F_;
    const __nv_bfloat16* wLoP = gW_lo + fB * F_;

    float acc[2][8][4];
#pragma unroll
    for (int m = 0; m < 2; m++)
#pragma unroll
        for (int n = 0; n < 8; n++)
#pragma unroll
            for (int q = 0; q < 4; q++) acc[m][n][q] = 0.f;

    uint32_t hw[4], lw[4];

    // ---- prologue: A(0) from h, B(0) via cp.async ----
    {
        float4 v0 = *(const float4*)(hP + jg);
        float4 v1 = *(const float4*)(hP + jg + 4);
        split_pair(v0.x, v0.y, hw[0], lw[0]);
        split_pair(v0.z, v0.w, hw[1], lw[1]);
        split_pair(v1.x, v1.y, hw[2], lw[2]);
        split_pair(v1.z, v1.w, hw[3], lw[3]);

        uint32_t dH = smBase + 2 * A_BYTES + (uint32_t)(fB * BST + hB) * 2u;
        cp_async16(dH,      wHiP + hB);
        cp_async16(dH + 16, wHiP + hB + 8);
        cp_async16(dH + B_BYTES,      wLoP + hB);
        cp_async16(dH + B_BYTES + 16, wLoP + hB + 8);
        CP_COMMIT();

        uint32_t off = (uint32_t)(ig * AST + jg) * 2u;
        asm volatile("st.shared.v4.b32 [%0], {%1,%2,%3,%4};"
                     :: "r"(smBase + off), "r"(hw[0]), "r"(hw[1]), "r"(hw[2]), "r"(hw[3]));
        asm volatile("st.shared.v4.b32 [%0], {%1,%2,%3,%4};"
                     :: "r"(smBase + A_BYTES + off), "r"(lw[0]), "r"(lw[1]), "r"(lw[2]), "r"(lw[3]));
        CP_WAIT0();
    }
    __syncthreads();

    for (int c = 0; c < 8; ++c) {
        const uint32_t sb   = smBase + (c & 1) * STAGE;
        const uint32_t sbN  = smBase + ((c + 1) & 1) * STAGE;
        const uint32_t aHiS = sb;
        const uint32_t aLoS = sb + A_BYTES;
        const uint32_t bHiS = sb + 2 * A_BYTES;
        const uint32_t bLoS = bHiS + B_BYTES;
        const bool doNext = (c + 1 < 8);
        const int  kn = (c + 1) * KC2;

        float4 ph0, ph1;
        if (doNext) {
            uint32_t dH = sbN + 2 * A_BYTES + (uint32_t)(fB * BST + hB) * 2u;
            cp_async16(dH,      wHiP + kn + hB);
            cp_async16(dH + 16, wHiP + kn + hB + 8);
            cp_async16(dH + B_BYTES,      wLoP + kn + hB);
            cp_async16(dH + B_BYTES + 16, wLoP + kn + hB + 8);
            CP_COMMIT();
            ph0 = *(const float4*)(hP + kn + jg);
            ph1 = *(const float4*)(hP + kn + jg + 4);
        }

        // ---- MMA(c) ----
#pragma unroll
        for (int ks = 0; ks < 2; ++ks) {
            const int k0 = ks * 16;
            uint32_t ah[2][4], al[2][4];
#pragma unroll
            for (int mt = 0; mt < 2; ++mt) {
                int arow = wm * 32 + mt * 16 + (lane & 15);
                uint32_t aoff = (uint32_t)(arow * AST + k0 + ((lane >> 4) << 3)) * 2u;
                ldm_x4(ah[mt][0], ah[mt][1], ah[mt][2], ah[mt][3], aHiS + aoff);
                ldm_x4(al[mt][0], al[mt][1], al[mt][2], al[mt][3], aLoS + aoff);
            }
#pragma unroll
            for (int pr = 0; pr < 4; ++pr) {
                int n0   = wn * 64 + pr * 16;
                int rowB = n0 + (lane & 7) + ((lane >> 4) << 3);
                int colB = k0 + (((lane >> 3) & 1) << 3);
                uint32_t boff = (uint32_t)(rowB * BST + colB) * 2u;
                uint32_t bh0, bh1, bh2, bh3, bl0, bl1, bl2, bl3;
                ldm_x4(bh0, bh1, bh2, bh3, bHiS + boff);
                ldm_x4(bl0, bl1, bl2, bl3, bLoS + boff);
                mma_bf16(acc[0][pr * 2],     ah[0], bh0, bh1);
                mma_bf16(acc[1][pr * 2],     ah[1], bh0, bh1);
                mma_bf16(acc[0][pr * 2 + 1], ah[0], bh2, bh3);
                mma_bf16(acc[1][pr * 2 + 1], ah[1], bh2, bh3);
                mma_bf16(acc[0][pr * 2],     ah[0], bl0, bl1);
                mma_bf16(acc[1][pr * 2],     ah[1], bl0, bl1);
                mma_bf16(acc[0][pr * 2 + 1], ah[0], bl2, bl3);
                mma_bf16(acc[1][pr * 2 + 1], ah[1], bl2, bl3);
                mma_bf16(acc[0][pr * 2],     al[0], bh0, bh1);
                mma_bf16(acc[1][pr * 2],     al[1], bh0, bh1);
                mma_bf16(acc[0][pr * 2 + 1], al[0], bh2, bh3);
                mma_bf16(acc[1][pr * 2 + 1], al[1], bh2, bh3);
            }
        }

        if (doNext) {
            split_pair(ph0.x, ph0.y, hw[0], lw[0]);
            split_pair(ph0.z, ph0.w, hw[1], lw[1]);
            split_pair(ph1.x, ph1.y, hw[2], lw[2]);
            split_pair(ph1.z, ph1.w, hw[3], lw[3]);
            uint32_t off = (uint32_t)(ig * AST + jg) * 2u;
            asm volatile("st.shared.v4.b32 [%0], {%1,%2,%3,%4};"
                         :: "r"(sbN + off), "r"(hw[0]), "r"(hw[1]), "r"(hw[2]), "r"(hw[3]));
            asm volatile("st.shared.v4.b32 [%0], {%1,%2,%3,%4};"
                         :: "r"(sbN + A_BYTES + off), "r"(lw[0]), "r"(lw[1]), "r"(lw[2]), "r"(lw[3]));
            CP_WAIT0();
        }
        __syncthreads();
    }

    // ---- epilogue part 1: bias, s1/s2 reduction ----
    const int g  = lane >> 2;
    const int tq = lane & 3;
#pragma unroll
    for (int mt = 0; mt < 2; ++mt) {
        int r0l = wm * 32 + mt * 16 + g;
        int r1l = r0l + 8;
        float a1_0 = 0.f, a2_0 = 0.f, a1_1 = 0.f, a2_1 = 0.f;
#pragma unroll
        for (int nt = 0; nt < 8; ++nt) {
            int col = wn * 64 + nt * 8 + 2 * tq;
            float b0 = sWb[col], b1 = sWb[col + 1];
            float i0v = sAi[col], i1v = sAi[col + 1];
            float j0v = sAj[col], j1v = sAj[col + 1];
            acc[mt][nt][0] += b0; acc[mt][nt][1] += b1;
            acc[mt][nt][2] += b0; acc[mt][nt][3] += b1;
            a1_0 = fmaf(acc[mt][nt][0], i0v, fmaf(acc[mt][nt][1], i1v, a1_0));
            a2_0 = fmaf(acc[mt][nt][0], j0v, fmaf(acc[mt][nt][1], j1v, a2_0));
            a1_1 = fmaf(acc[mt][nt][2], i0v, fmaf(acc[mt][nt][3], i1v, a1_1));
            a2_1 = fmaf(acc[mt][nt][2], j0v, fmaf(acc[mt][nt][3], j1v, a2_1));
        }
#pragma unroll
        for (int off = 1; off <= 2; off <<= 1) {
            a1_0 += __shfl_xor_sync(0xffffffffu, a1_0, off);
            a2_0 += __shfl_xor_sync(0xffffffffu, a2_0, off);
            a1_1 += __shfl_xor_sync(0xffffffffu, a1_1, off);
            a2_1 += __shfl_xor_sync(0xffffffffu, a2_1, off);
        }
        if (tq == 0) {
            red1[r0l][wn] = a1_0; red2[r0l][wn] = a2_0;
            red1[r1l][wn] = a1_1; red2[r1l][wn] = a2_1;
        }
    }
    __syncthreads();
    if (t < 128) {
        g_s1[row0 + t] = red1[t][0] + red1[t][1] + red1[t][2] + red1[t][3] + aib[0];
        g_s2[row0 + t] = red2[t][0] + red2[t][1] + red2[t][2] + red2[t][3] + ajb[0];
    }

    // ---- epilogue part 2: FUSED transpose + bf16 split, two 128f passes ----
    float* ts = (float*)smRaw;
    const int b   = row0 >> 11;
    const int jlo = row0 & (N_ - 1);
    const int fLoc = t >> 2;                 // 0..127
    const int jseg = (t & 3) * 32;           // 0,32,64,96

#pragma unroll
    for (int fh = 0; fh < 2; ++fh) {
        __syncthreads();
        if ((wn >> 1) == fh) {
#pragma unroll
            for (int mt = 0; mt < 2; ++mt) {
                int r0l = wm * 32 + mt * 16 + g;
                int r1l = r0l + 8;
#pragma unroll
                for (int nt = 0; nt < 8; ++nt) {
                    int colL = (wn & 1) * 64 + nt * 8 + 2 * tq;
                    *(float2*)&ts[r0l * 132 + colL] =
                        make_float2(acc[mt][nt][0], acc[mt][nt][1]);
                    *(float2*)&ts[r1l * 132 + colL] =
                        make_float2(acc[mt][nt][2], acc[mt][nt][3]);
                }
            }
        }
        __syncthreads();
        uint32_t hp[16], lp[16];
#pragma unroll
        for (int e = 0; e < 32; e += 2) {
            float v0 = ts[(jseg + e) * 132 + fLoc];
            float v1 = ts[(jseg + e + 1) * 132 + fLoc];
            split_pair(v0, v1, hp[e >> 1], lp[e >> 1]);
        }
        size_t dst = ((size_t)(b * F_ + fh * 128 + fLoc)) * N_ + jlo + jseg;
        uint4* dh = (uint4*)(g_WhT_hi + dst);
        uint4* dl = (uint4*)(g_WhT_lo + dst);
        dh[0] = make_uint4(hp[0],  hp[1],  hp[2],  hp[3]);
        dh[1] = make_uint4(hp[4],  hp[5],  hp[6],  hp[7]);
        dh[2] = make_uint4(hp[8],  hp[9],  hp[10], hp[11]);
        dh[3] = make_uint4(hp[12], hp[13], hp[14], hp[15]);
        dl[0] = make_uint4(lp[0],  lp[1],  lp[2],  lp[3]);
        dl[1] = make_uint4(lp[4],  lp[5],  lp[6],  lp[7]);
        dl[2] = make_uint4(lp[8],  lp[9],  lp[10], lp[11]);
        dl[3] = make_uint4(lp[12], lp[13], lp[14], lp[15]);
    }
}

// ---------------------------------------------------------------------------
// Kernel 2: HMMA attention GEMM (proven best: 512 thr, 128i x 256f, KC=32)
// ---------------------------------------------------------------------------
#define NCH2  (N_ / KC2)                  // 64 chunks

__global__ void __launch_bounds__(512, 1) k2_attn(
    const int* __restrict__ adj, float* __restrict__ out)
{
    extern __shared__ __align__(16) char smRaw[];
    __shared__ float s1S[128];
    __shared__ __align__(16) float s2S[N_];
    __shared__ float rsS[128][4];
    __shared__ float rInv[128];

    const int t    = threadIdx.x;
    const int lane = t & 31;
    const int wid  = t >> 5;
    const int wm   = wid & 3;
    const int wn   = wid >> 2;
    const int b    = blockIdx.x >> 4;
    const int i0   = (blockIdx.x & 15) * 128;

    const uint32_t smBase = smem_u32(smRaw);

    if (t < 128) s1S[t] = g_s1[b * N_ + i0 + t];
    {
        const float4* s2g = (const float4*)(g_s2 + b * N_);
#pragma unroll
        for (int k = t; k < N_ / 4; k += 512) ((float4*)s2S)[k] = s2g[k];
    }

    const int ig = t >> 2;
    const int jg = (t & 3) * 8;
    const int fB = t >> 1;
    const int hB = (t & 1) * 16;

    const int* adjP = adj + (size_t)(b * N_ + i0 + ig) * N_;
    const __nv_bfloat16* bhP = g_WhT_hi + (size_t)(b * F_ + fB) * N_;
    const __nv_bfloat16* blP = g_WhT_lo + (size_t)(b * F_ + fB) * N_;

    float acc[2][8][4];
#pragma unroll
    for (int m = 0; m < 2; m++)
#pragma unroll
        for (int n = 0; n < 8; n++)
#pragma unroll
            for (int q = 0; q < 4; q++) acc[m][n][q] = 0.f;
    float lsum = 0.f;

    uint32_t hw[4], lw[4];

    __syncthreads();

    {
        int4 a0 = *(const int4*)(adjP + jg);
        int4 a1 = *(const int4*)(adjP + jg + 4);
        const float s1v = s1S[ig];
        make_w_pair(s1v, a0.x, a0.y, s2S[jg + 0], s2S[jg + 1], lsum, hw[0], lw[0]);
        make_w_pair(s1v, a0.z, a0.w, s2S[jg + 2], s2S[jg + 3], lsum, hw[1], lw[1]);
        make_w_pair(s1v, a1.x, a1.y, s2S[jg + 4], s2S[jg + 5], lsum, hw[2], lw[2]);
        make_w_pair(s1v, a1.z, a1.w, s2S[jg + 6], s2S[jg + 7], lsum, hw[3], lw[3]);

        uint32_t dH = smBase + 2 * A_BYTES + (uint32_t)(fB * BST + hB) * 2u;
        cp_async16(dH,      bhP + hB);
        cp_async16(dH + 16, bhP + hB + 8);
        cp_async16(dH + B_BYTES,      blP + hB);
        cp_async16(dH + B_BYTES + 16, blP + hB + 8);
        CP_COMMIT();

        uint32_t off = (uint32_t)(ig * AST + jg) * 2u;
        asm volatile("st.shared.v4.b32 [%0], {%1,%2,%3,%4};"
                     :: "r"(smBase + off), "r"(hw[0]), "r"(hw[1]), "r"(hw[2]), "r"(hw[3]));
        asm volatile("st.shared.v4.b32 [%0], {%1,%2,%3,%4};"
                     :: "r"(smBase + A_BYTES + off), "r"(lw[0]), "r"(lw[1]), "r"(lw[2]), "r"(lw[3]));
        CP_WAIT0();
    }
    __syncthreads();

    for (int c = 0; c < NCH2; ++c) {
        const uint32_t sb   = smBase + (c & 1) * STAGE;
        const uint32_t sbN  = smBase + ((c + 1) & 1) * STAGE;
        const uint32_t aHiS = sb;
        const uint32_t aLoS = sb + A_BYTES;
        const uint32_t bHiS = sb + 2 * A_BYTES;
        const uint32_t bLoS = bHiS + B_BYTES;
        const bool doNext = (c + 1 < NCH2);
        const int  jn = (c + 1) * KC2;

        int4 pA0, pA1;
        if (doNext) {
            uint32_t dH = sbN + 2 * A_BYTES + (uint32_t)(fB * BST + hB) * 2u;
            cp_async16(dH,      bhP + jn + hB);
            cp_async16(dH + 16, bhP + jn + hB + 8);
            cp_async16(dH + B_BYTES,      blP + jn + hB);
            cp_async16(dH + B_BYTES + 16, blP + jn + hB + 8);
            CP_COMMIT();
            pA0 = *(const int4*)(adjP + jn + jg);
            pA1 = *(const int4*)(adjP + jn + jg + 4);
        }
        const float s1v = s1S[ig];

#pragma unroll
        for (int ks = 0; ks < 2; ++ks) {
            const int k0 = ks * 16;
            uint32_t ah[2][4], al[2][4];
#pragma unroll
            for (int mt = 0; mt < 2; ++mt) {
                int arow = wm * 32 + mt * 16 + (lane & 15);
                uint32_t aoff = (uint32_t)(arow * AST + k0 + ((lane >> 4) << 3)) * 2u;
                ldm_x4(ah[mt][0], ah[mt][1], ah[mt][2], ah[mt][3], aHiS + aoff);
                ldm_x4(al[mt][0], al[mt][1], al[mt][2], al[mt][3], aLoS + aoff);
            }
#pragma unroll
            for (int pr = 0; pr < 4; ++pr) {
                int n0   = wn * 64 + pr * 16;
                int rowB = n0 + (lane & 7) + ((lane >> 4) << 3);
                int colB = k0 + (((lane >> 3) & 1) << 3);
                uint32_t boff = (uint32_t)(rowB * BST + colB) * 2u;
                uint32_t bh0, bh1, bh2, bh3, bl0, bl1, bl2, bl3;
                ldm_x4(bh0, bh1, bh2, bh3, bHiS + boff);
                ldm_x4(bl0, bl1, bl2, bl3, bLoS + boff);
                mma_bf16(acc[0][pr * 2],     ah[0], bh0, bh1);
                mma_bf16(acc[1][pr * 2],     ah[1], bh0, bh1);
                mma_bf16(acc[0][pr * 2 + 1], ah[0], bh2, bh3);
                mma_bf16(acc[1][pr * 2 + 1], ah[1], bh2, bh3);
                mma_bf16(acc[0][pr * 2],     ah[0], bl0, bl1);
                mma_bf16(acc[1][pr * 2],     ah[1], bl0, bl1);
                mma_bf16(acc[0][pr * 2 + 1], ah[0], bl2, bl3);
                mma_bf16(acc[1][pr * 2 + 1], ah[1], bl2, bl3);
                mma_bf16(acc[0][pr * 2],     al[0], bh0, bh1);
                mma_bf16(acc[1][pr * 2],     al[1], bh0, bh1);
                mma_bf16(acc[0][pr * 2 + 1], al[0], bh2, bh3);
                mma_bf16(acc[1][pr * 2 + 1], al[1], bh2, bh3);

                if (doNext && ks == 1) {
                    int a0 = (pr < 2) ? ((pr == 0) ? pA0.x : pA0.z)
                                      : ((pr == 2) ? pA1.x : pA1.z);
                    int a1 = (pr < 2) ? ((pr == 0) ? pA0.y : pA0.w)
                                      : ((pr == 2) ? pA1.y : pA1.w);
                    make_w_pair(s1v, a0, a1,
                                s2S[jn + jg + 2 * pr], s2S[jn + jg + 2 * pr + 1],
                                lsum, hw[pr], lw[pr]);
                }
            }
        }

        if (doNext) {
            uint32_t off = (uint32_t)(ig * AST + jg) * 2u;
            asm volatile("st.shared.v4.b32 [%0], {%1,%2,%3,%4};"
                         :: "r"(sbN + off), "r"(hw[0]), "r"(hw[1]), "r"(hw[2]), "r"(hw[3]));
            asm volatile("st.shared.v4.b32 [%0], {%1,%2,%3,%4};"
                         :: "r"(sbN + A_BYTES + off), "r"(lw[0]), "r"(lw[1]), "r"(lw[2]), "r"(lw[3]));
            CP_WAIT0();
        }
        __syncthreads();
    }

    rsS[ig][t & 3] = lsum;
    __syncthreads();
    if (t < 128) rInv[t] = 1.f / (rsS[t][0] + rsS[t][1] + rsS[t][2] + rsS[t][3]);
    __syncthreads();

    const int g  = lane >> 2;
    const int tq = lane & 3;
#pragma unroll
    for (int mt = 0; mt < 2; ++mt) {
        int r0l = wm * 32 + mt * 16 + g;
        int r1l = r0l + 8;
        float inv0 = rInv[r0l], inv1 = rInv[r1l];
        size_t o0 = ((size_t)(b * N_ + i0 + r0l)) * F_;
        size_t o1 = ((size_t)(b * N_ + i0 + r1l)) * F_;
#pragma unroll
        for (int nt = 0; nt < 8; ++nt) {
            int col = wn * 64 + nt * 8 + 2 * tq;
            float x0 = acc[mt][nt][0] * inv0;
            float x1 = acc[mt][nt][1] * inv0;
            float x2 = acc[mt][nt][2] * inv1;
            float x3 = acc[mt][nt][3] * inv1;
            x0 = (x0 > 0.f) ? x0 : expm1f(x0);
            x1 = (x1 > 0.f) ? x1 : expm1f(x1);
            x2 = (x2 > 0.f) ? x2 : expm1f(x2);
            x3 = (x3 > 0.f) ? x3 : expm1f(x3);
            *(float2*)(out + o0 + col) = make_float2(x0, x1);
            *(float2*)(out + o1 + col) = make_float2(x2, x3);
        }
    }
}

// ---------------------------------------------------------------------------
extern "C" void kernel_launch(void* const* d_in, const int* in_sizes, int n_in,
                              void* d_out, int out_size)
{
    const float* h   = (const float*)d_in[0];
    const int*   adj = (const int*)  d_in[1];
    const float* Ww  = (const float*)d_in[2];
    const float* Wb  = (const float*)d_in[3];
    const float* aiw = (const float*)d_in[4];
    const float* aib = (const float*)d_in[5];
    const float* ajw = (const float*)d_in[6];
    const float* ajb = (const float*)d_in[7];
    float* out = (float*)d_out;

    static bool attrDone = false;
    if (!attrDone) {
        cudaFuncSetAttribute(k1_hmma, cudaFuncAttributeMaxDynamicSharedMemorySize,
                             DYN_SMEM);
        cudaFuncSetAttribute(k2_attn, cudaFuncAttributeMaxDynamicSharedMemorySize,
                             DYN_SMEM);
        attrDone = true;
    }

    k0_convW<<<128, 256>>>(Ww);
    k1_hmma<<<(B_ * N_) / 128, 512, DYN_SMEM>>>(h, Wb, aiw, aib, ajw, ajb);
    k2_attn<<<B_ * (N_ / 128), 512, DYN_SMEM>>>(adj, out);
}

// round 16
// speedup vs baseline: 1.1242x; 1.0033x over previous
#include <cuda_runtime.h>
#include <cuda_bf16.h>
#include <math.h>
#include <cstdint>
#include <cstddef>

#define B_   8
#define N_   2048
#define F_   256
#define ALPHA 0.2f

// ---------------- device scratch (allocation-free rule) ----------------
__device__ float g_s1[B_ * N_];
__device__ float g_s2[B_ * N_];
__device__ __nv_bfloat16 g_WhT_hi[B_ * F_ * N_];   // [b][f][j]
__device__ __nv_bfloat16 g_WhT_lo[B_ * F_ * N_];
__device__ __nv_bfloat16 gW_hi[F_ * F_];           // W split, [out][k]
__device__ __nv_bfloat16 gW_lo[F_ * F_];

__device__ __forceinline__ uint32_t smem_u32(const void* p) {
    uint32_t a;
    asm("{ .reg .u64 t; cvta.to.shared.u64 t, %1; cvt.u32.u64 %0, t; }"
        : "=r"(a) : "l"(p));
    return a;
}
__device__ __forceinline__ void ldm_x4(uint32_t& r0, uint32_t& r1,
                                       uint32_t& r2, uint32_t& r3, uint32_t addr) {
    asm volatile("ldmatrix.sync.aligned.m8n8.x4.shared.b16 {%0,%1,%2,%3}, [%4];"
                 : "=r"(r0), "=r"(r1), "=r"(r2), "=r"(r3) : "r"(addr));
}
__device__ __forceinline__ void mma_bf16(float* d, const uint32_t* a,
                                         uint32_t b0, uint32_t b1) {
    asm volatile(
        "mma.sync.aligned.m16n8k16.row.col.f32.bf16.bf16.f32 "
        "{%0,%1,%2,%3}, {%4,%5,%6,%7}, {%8,%9}, {%0,%1,%2,%3};"
        : "+f"(d[0]), "+f"(d[1]), "+f"(d[2]), "+f"(d[3])
        : "r"(a[0]), "r"(a[1]), "r"(a[2]), "r"(a[3]), "r"(b0), "r"(b1));
}
__device__ __forceinline__ void cp_async16(uint32_t dst, const void* src) {
    asm volatile("cp.async.cg.shared.global [%0], [%1], 16;"
                 :: "r"(dst), "l"(src) : "memory");
}
#define CP_COMMIT() asm volatile("cp.async.commit_group;" ::: "memory")
#define CP_WAIT0()  asm volatile("cp.async.wait_group 0;" ::: "memory")

__device__ __forceinline__ void split_pair(float v0, float v1,
                                           uint32_t& hiP, uint32_t& loP) {
    __nv_bfloat16 h0 = __float2bfloat16(v0), h1 = __float2bfloat16(v1);
    float r0 = v0 - __bfloat162float(h0);
    float r1 = v1 - __bfloat162float(h1);
    __nv_bfloat16 l0 = __float2bfloat16(r0), l1 = __float2bfloat16(r1);
    __nv_bfloat162 hp = __halves2bfloat162(h0, h1);
    __nv_bfloat162 lp = __halves2bfloat162(l0, l1);
    hiP = *(uint32_t*)&hp;
    loP = *(uint32_t*)&lp;
}

// w-pair: leaky+exp+mask, bf16 hi/lo split, rowsum accumulate
__device__ __forceinline__ void make_w_pair(float s1v, int a0, int a1,
                                            float s20, float s21,
                                            float& lsum, uint32_t& hiP, uint32_t& loP)
{
    float x0 = s1v + s20; x0 = fmaxf(x0, ALPHA * x0);
    float x1 = s1v + s21; x1 = fmaxf(x1, ALPHA * x1);
    float w0 = (a0 > 0) ? __expf(x0) : 0.f;
    float w1 = (a1 > 0) ? __expf(x1) : 0.f;
    lsum += w0 + w1;
    split_pair(w0, w1, hiP, loP);
}

// ---------------------------------------------------------------------------
// Kernel 0: split W (256x256 fp32, [out][k]) into bf16 hi/lo.
// ---------------------------------------------------------------------------
__global__ void __launch_bounds__(256) k0_convW(const float* __restrict__ Ww)
{
    int idx = (blockIdx.x * 256 + threadIdx.x) * 2;
    float2 v = *(const float2*)(Ww + idx);
    uint32_t hw, lw;
    split_pair(v.x, v.y, hw, lw);
    *(uint32_t*)(gW_hi + idx) = hw;
    *(uint32_t*)(gW_lo + idx) = lw;
}

// ---------------------------------------------------------------------------
// Shared tile constants (k1_hmma and k2 use the same skeleton)
// ---------------------------------------------------------------------------
#define KC2   32
#define AST   40
#define BST   40
#define A_BYTES (128 * AST * 2)           // 10240
#define B_BYTES (256 * BST * 2)           // 20480
#define STAGE   (2 * A_BYTES + 2 * B_BYTES)   // 61440
#define DYN_SMEM (2 * STAGE)                  // 122880

// ---------------------------------------------------------------------------
// Kernel 1: HMMA Wh = h @ W^T (+bias, s1/s2), bf16 3-term split.
//   CTA 128 rows x 256 out, 512 thr, 8 k-chunks of 32.
//   FUSED epilogue: stages the output tile in smem (2 x 128f passes) and
//   writes WhT hi/lo directly (transpose+split) — no g_Wh round-trip.
// ---------------------------------------------------------------------------
__global__ void __launch_bounds__(512, 1) k1_hmma(
    const float* __restrict__ h,  const float* __restrict__ Wb,
    const float* __restrict__ aiw, const float* __restrict__ aib,
    const float* __restrict__ ajw, const float* __restrict__ ajb)
{
    extern __shared__ __align__(16) char smRaw[];
    __shared__ float sWb[F_], sAi[F_], sAj[F_];
    __shared__ float red1[128][4], red2[128][4];

    const int t    = threadIdx.x;
    const int lane = t & 31;
    const int wid  = t >> 5;
    const int wm   = wid & 3;
    const int wn   = wid >> 2;
    const int row0 = blockIdx.x * 128;

    const uint32_t smBase = smem_u32(smRaw);

    if (t < F_) { sWb[t] = Wb[t]; sAi[t] = aiw[t]; sAj[t] = ajw[t]; }

    // ---- roles (identical to k2) ----
    const int ig = t >> 2;                   // A row 0..127
    const int jg = (t & 3) * 8;              // 8-k subgroup
    const int fB = t >> 1;                   // B row (out) 0..255
    const int hB = (t & 1) * 16;

    const float* hP = h + (size_t)(row0 + ig) * F_;
    const __nv_bfloat16* wHiP = gW_hi + fB * F_;
    const __nv_bfloat16* wLoP = gW_lo + fB * F_;

    float acc[2][8][4];
#pragma unroll
    for (int m = 0; m < 2; m++)
#pragma unroll
        for (int n = 0; n < 8; n++)
#pragma unroll
            for (int q = 0; q < 4; q++) acc[m][n][q] = 0.f;

    uint32_t hw[4], lw[4];

    // ---- prologue: A(0) from h, B(0) via cp.async ----
    {
        float4 v0 = *(const float4*)(hP + jg);
        float4 v1 = *(const float4*)(hP + jg + 4);
        split_pair(v0.x, v0.y, hw[0], lw[0]);
        split_pair(v0.z, v0.w, hw[1], lw[1]);
        split_pair(v1.x, v1.y, hw[2], lw[2]);
        split_pair(v1.z, v1.w, hw[3], lw[3]);

        uint32_t dH = smBase + 2 * A_BYTES + (uint32_t)(fB * BST + hB) * 2u;
        cp_async16(dH,      wHiP + hB);
        cp_async16(dH + 16, wHiP + hB + 8);
        cp_async16(dH + B_BYTES,      wLoP + hB);
        cp_async16(dH + B_BYTES + 16, wLoP + hB + 8);
        CP_COMMIT();

        uint32_t off = (uint32_t)(ig * AST + jg) * 2u;
        asm volatile("st.shared.v4.b32 [%0], {%1,%2,%3,%4};"
                     :: "r"(smBase + off), "r"(hw[0]), "r"(hw[1]), "r"(hw[2]), "r"(hw[3]));
        asm volatile("st.shared.v4.b32 [%0], {%1,%2,%3,%4};"
                     :: "r"(smBase + A_BYTES + off), "r"(lw[0]), "r"(lw[1]), "r"(lw[2]), "r"(lw[3]));
        CP_WAIT0();
    }
    __syncthreads();

    for (int c = 0; c < 8; ++c) {
        const uint32_t sb   = smBase + (c & 1) * STAGE;
        const uint32_t sbN  = smBase + ((c + 1) & 1) * STAGE;
        const uint32_t aHiS = sb;
        const uint32_t aLoS = sb + A_BYTES;
        const uint32_t bHiS = sb + 2 * A_BYTES;
        const uint32_t bLoS = bHiS + B_BYTES;
        const bool doNext = (c + 1 < 8);
        const int  kn = (c + 1) * KC2;

        float4 ph0, ph1;
        if (doNext) {
            uint32_t dH = sbN + 2 * A_BYTES + (uint32_t)(fB * BST + hB) * 2u;
            cp_async16(dH,      wHiP + kn + hB);
            cp_async16(dH + 16, wHiP + kn + hB + 8);
            cp_async16(dH + B_BYTES,      wLoP + kn + hB);
            cp_async16(dH + B_BYTES + 16, wLoP + kn + hB + 8);
            CP_COMMIT();
            ph0 = *(const float4*)(hP + kn + jg);
            ph1 = *(const float4*)(hP + kn + jg + 4);
        }

        // ---- MMA(c) ----
#pragma unroll
        for (int ks = 0; ks < 2; ++ks) {
            const int k0 = ks * 16;
            uint32_t ah[2][4], al[2][4];
#pragma unroll
            for (int mt = 0; mt < 2; ++mt) {
                int arow = wm * 32 + mt * 16 + (lane & 15);
                uint32_t aoff = (uint32_t)(arow * AST + k0 + ((lane >> 4) << 3)) * 2u;
                ldm_x4(ah[mt][0], ah[mt][1], ah[mt][2], ah[mt][3], aHiS + aoff);
                ldm_x4(al[mt][0], al[mt][1], al[mt][2], al[mt][3], aLoS + aoff);
            }
#pragma unroll
            for (int pr = 0; pr < 4; ++pr) {
                int n0   = wn * 64 + pr * 16;
                int rowB = n0 + (lane & 7) + ((lane >> 4) << 3);
                int colB = k0 + (((lane >> 3) & 1) << 3);
                uint32_t boff = (uint32_t)(rowB * BST + colB) * 2u;
                uint32_t bh0, bh1, bh2, bh3, bl0, bl1, bl2, bl3;
                ldm_x4(bh0, bh1, bh2, bh3, bHiS + boff);
                ldm_x4(bl0, bl1, bl2, bl3, bLoS + boff);
                mma_bf16(acc[0][pr * 2],     ah[0], bh0, bh1);
                mma_bf16(acc[1][pr * 2],     ah[1], bh0, bh1);
                mma_bf16(acc[0][pr * 2 + 1], ah[0], bh2, bh3);
                mma_bf16(acc[1][pr * 2 + 1], ah[1], bh2, bh3);
                mma_bf16(acc[0][pr * 2],     ah[0], bl0, bl1);
                mma_bf16(acc[1][pr * 2],     ah[1], bl0, bl1);
                mma_bf16(acc[0][pr * 2 + 1], ah[0], bl2, bl3);
                mma_bf16(acc[1][pr * 2 + 1], ah[1], bl2, bl3);
                mma_bf16(acc[0][pr * 2],     al[0], bh0, bh1);
                mma_bf16(acc[1][pr * 2],     al[1], bh0, bh1);
                mma_bf16(acc[0][pr * 2 + 1], al[0], bh2, bh3);
                mma_bf16(acc[1][pr * 2 + 1], al[1], bh2, bh3);
            }
        }

        if (doNext) {
            split_pair(ph0.x, ph0.y, hw[0], lw[0]);
            split_pair(ph0.z, ph0.w, hw[1], lw[1]);
            split_pair(ph1.x, ph1.y, hw[2], lw[2]);
            split_pair(ph1.z, ph1.w, hw[3], lw[3]);
            uint32_t off = (uint32_t)(ig * AST + jg) * 2u;
            asm volatile("st.shared.v4.b32 [%0], {%1,%2,%3,%4};"
                         :: "r"(sbN + off), "r"(hw[0]), "r"(hw[1]), "r"(hw[2]), "r"(hw[3]));
            asm volatile("st.shared.v4.b32 [%0], {%1,%2,%3,%4};"
                         :: "r"(sbN + A_BYTES + off), "r"(lw[0]), "r"(lw[1]), "r"(lw[2]), "r"(lw[3]));
            CP_WAIT0();
        }
        __syncthreads();
    }

    // ---- epilogue part 1: bias, s1/s2 reduction ----
    const int g  = lane >> 2;
    const int tq = lane & 3;
#pragma unroll
    for (int mt = 0; mt < 2; ++mt) {
        int r0l = wm * 32 + mt * 16 + g;
        int r1l = r0l + 8;
        float a1_0 = 0.f, a2_0 = 0.f, a1_1 = 0.f, a2_1 = 0.f;
#pragma unroll
        for (int nt = 0; nt < 8; ++nt) {
            int col = wn * 64 + nt * 8 + 2 * tq;
            float b0 = sWb[col], b1 = sWb[col + 1];
            float i0v = sAi[col], i1v = sAi[col + 1];
            float j0v = sAj[col], j1v = sAj[col + 1];
            acc[mt][nt][0] += b0; acc[mt][nt][1] += b1;
            acc[mt][nt][2] += b0; acc[mt][nt][3] += b1;
            a1_0 = fmaf(acc[mt][nt][0], i0v, fmaf(acc[mt][nt][1], i1v, a1_0));
            a2_0 = fmaf(acc[mt][nt][0], j0v, fmaf(acc[mt][nt][1], j1v, a2_0));
            a1_1 = fmaf(acc[mt][nt][2], i0v, fmaf(acc[mt][nt][3], i1v, a1_1));
            a2_1 = fmaf(acc[mt][nt][2], j0v, fmaf(acc[mt][nt][3], j1v, a2_1));
        }
#pragma unroll
        for (int off = 1; off <= 2; off <<= 1) {
            a1_0 += __shfl_xor_sync(0xffffffffu, a1_0, off);
            a2_0 += __shfl_xor_sync(0xffffffffu, a2_0, off);
            a1_1 += __shfl_xor_sync(0xffffffffu, a1_1, off);
            a2_1 += __shfl_xor_sync(0xffffffffu, a2_1, off);
        }
        if (tq == 0) {
            red1[r0l][wn] = a1_0; red2[r0l][wn] = a2_0;
            red1[r1l][wn] = a1_1; red2[r1l][wn] = a2_1;
        }
    }
    __syncthreads();
    if (t < 128) {
        g_s1[row0 + t] = red1[t][0] + red1[t][1] + red1[t][2] + red1[t][3] + aib[0];
        g_s2[row0 + t] = red2[t][0] + red2[t][1] + red2[t][2] + red2[t][3] + ajb[0];
    }

    // ---- epilogue part 2: FUSED transpose + bf16 split, two 128f passes ----
    float* ts = (float*)smRaw;
    const int b   = row0 >> 11;
    const int jlo = row0 & (N_ - 1);
    const int fLoc = t >> 2;                 // 0..127
    const int jseg = (t & 3) * 32;           // 0,32,64,96

#pragma unroll
    for (int fh = 0; fh < 2; ++fh) {
        __syncthreads();
        if ((wn >> 1) == fh) {
#pragma unroll
            for (int mt = 0; mt < 2; ++mt) {
                int r0l = wm * 32 + mt * 16 + g;
                int r1l = r0l + 8;
#pragma unroll
                for (int nt = 0; nt < 8; ++nt) {
                    int colL = (wn & 1) * 64 + nt * 8 + 2 * tq;
                    *(float2*)&ts[r0l * 132 + colL] =
                        make_float2(acc[mt][nt][0], acc[mt][nt][1]);
                    *(float2*)&ts[r1l * 132 + colL] =
                        make_float2(acc[mt][nt][2], acc[mt][nt][3]);
                }
            }
        }
        __syncthreads();
        uint32_t hp[16], lp[16];
#pragma unroll
        for (int e = 0; e < 32; e += 2) {
            float v0 = ts[(jseg + e) * 132 + fLoc];
            float v1 = ts[(jseg + e + 1) * 132 + fLoc];
            split_pair(v0, v1, hp[e >> 1], lp[e >> 1]);
        }
        size_t dst = ((size_t)(b * F_ + fh * 128 + fLoc)) * N_ + jlo + jseg;
        uint4* dh = (uint4*)(g_WhT_hi + dst);
        uint4* dl = (uint4*)(g_WhT_lo + dst);
        dh[0] = make_uint4(hp[0],  hp[1],  hp[2],  hp[3]);
        dh[1] = make_uint4(hp[4],  hp[5],  hp[6],  hp[7]);
        dh[2] = make_uint4(hp[8],  hp[9],  hp[10], hp[11]);
        dh[3] = make_uint4(hp[12], hp[13], hp[14], hp[15]);
        dl[0] = make_uint4(lp[0],  lp[1],  lp[2],  lp[3]);
        dl[1] = make_uint4(lp[4],  lp[5],  lp[6],  lp[7]);
        dl[2] = make_uint4(lp[8],  lp[9],  lp[10], lp[11]);
        dl[3] = make_uint4(lp[12], lp[13], lp[14], lp[15]);
    }
}

// ---------------------------------------------------------------------------
// Kernel 2: HMMA attention GEMM (proven best: 512 thr, 128i x 256f, KC=32)
// ---------------------------------------------------------------------------
#define NCH2  (N_ / KC2)                  // 64 chunks

__global__ void __launch_bounds__(512, 1) k2_attn(
    const int* __restrict__ adj, float* __restrict__ out)
{
    extern __shared__ __align__(16) char smRaw[];
    __shared__ float s1S[128];
    __shared__ __align__(16) float s2S[N_];
    __shared__ float rsS[128][4];
    __shared__ float rInv[128];

    const int t    = threadIdx.x;
    const int lane = t & 31;
    const int wid  = t >> 5;
    const int wm   = wid & 3;
    const int wn   = wid >> 2;
    const int b    = blockIdx.x >> 4;
    const int i0   = (blockIdx.x & 15) * 128;

    const uint32_t smBase = smem_u32(smRaw);

    if (t < 128) s1S[t] = g_s1[b * N_ + i0 + t];
    {
        const float4* s2g = (const float4*)(g_s2 + b * N_);
#pragma unroll
        for (int k = t; k < N_ / 4; k += 512) ((float4*)s2S)[k] = s2g[k];
    }

    const int ig = t >> 2;
    const int jg = (t & 3) * 8;
    const int fB = t >> 1;
    const int hB = (t & 1) * 16;

    const int* adjP = adj + (size_t)(b * N_ + i0 + ig) * N_;
    const __nv_bfloat16* bhP = g_WhT_hi + (size_t)(b * F_ + fB) * N_;
    const __nv_bfloat16* blP = g_WhT_lo + (size_t)(b * F_ + fB) * N_;

    float acc[2][8][4];
#pragma unroll
    for (int m = 0; m < 2; m++)
#pragma unroll
        for (int n = 0; n < 8; n++)
#pragma unroll
            for (int q = 0; q < 4; q++) acc[m][n][q] = 0.f;
    float lsum = 0.f;

    uint32_t hw[4], lw[4];

    __syncthreads();

    {
        int4 a0 = *(const int4*)(adjP + jg);
        int4 a1 = *(const int4*)(adjP + jg + 4);
        const float s1v = s1S[ig];
        make_w_pair(s1v, a0.x, a0.y, s2S[jg + 0], s2S[jg + 1], lsum, hw[0], lw[0]);
        make_w_pair(s1v, a0.z, a0.w, s2S[jg + 2], s2S[jg + 3], lsum, hw[1], lw[1]);
        make_w_pair(s1v, a1.x, a1.y, s2S[jg + 4], s2S[jg + 5], lsum, hw[2], lw[2]);
        make_w_pair(s1v, a1.z, a1.w, s2S[jg + 6], s2S[jg + 7], lsum, hw[3], lw[3]);

        uint32_t dH = smBase + 2 * A_BYTES + (uint32_t)(fB * BST + hB) * 2u;
        cp_async16(dH,      bhP + hB);
        cp_async16(dH + 16, bhP + hB + 8);
        cp_async16(dH + B_BYTES,      blP + hB);
        cp_async16(dH + B_BYTES + 16, blP + hB + 8);
        CP_COMMIT();

        uint32_t off = (uint32_t)(ig * AST + jg) * 2u;
        asm volatile("st.shared.v4.b32 [%0], {%1,%2,%3,%4};"
                     :: "r"(smBase + off), "r"(hw[0]), "r"(hw[1]), "r"(hw[2]), "r"(hw[3]));
        asm volatile("st.shared.v4.b32 [%0], {%1,%2,%3,%4};"
                     :: "r"(smBase + A_BYTES + off), "r"(lw[0]), "r"(lw[1]), "r"(lw[2]), "r"(lw[3]));
        CP_WAIT0();
    }
    __syncthreads();

    for (int c = 0; c < NCH2; ++c) {
        const uint32_t sb   = smBase + (c & 1) * STAGE;
        const uint32_t sbN  = smBase + ((c + 1) & 1) * STAGE;
        const uint32_t aHiS = sb;
        const uint32_t aLoS = sb + A_BYTES;
        const uint32_t bHiS = sb + 2 * A_BYTES;
        const uint32_t bLoS = bHiS + B_BYTES;
        const bool doNext = (c + 1 < NCH2);
        const int  jn = (c + 1) * KC2;

        int4 pA0, pA1;
        if (doNext) {
            uint32_t dH = sbN + 2 * A_BYTES + (uint32_t)(fB * BST + hB) * 2u;
            cp_async16(dH,      bhP + jn + hB);
            cp_async16(dH + 16, bhP + jn + hB + 8);
            cp_async16(dH + B_BYTES,      blP + jn + hB);
            cp_async16(dH + B_BYTES + 16, blP + jn + hB + 8);
            CP_COMMIT();
            pA0 = *(const int4*)(adjP + jn + jg);
            pA1 = *(const int4*)(adjP + jn + jg + 4);
        }
        const float s1v = s1S[ig];

#pragma unroll
        for (int ks = 0; ks < 2; ++ks) {
            const int k0 = ks * 16;
            uint32_t ah[2][4], al[2][4];
#pragma unroll
            for (int mt = 0; mt < 2; ++mt) {
                int arow = wm * 32 + mt * 16 + (lane & 15);
                uint32_t aoff = (uint32_t)(arow * AST + k0 + ((lane >> 4) << 3)) * 2u;
                ldm_x4(ah[mt][0], ah[mt][1], ah[mt][2], ah[mt][3], aHiS + aoff);
                ldm_x4(al[mt][0], al[mt][1], al[mt][2], al[mt][3], aLoS + aoff);
            }
#pragma unroll
            for (int pr = 0; pr < 4; ++pr) {
                int n0   = wn * 64 + pr * 16;
                int rowB = n0 + (lane & 7) + ((lane >> 4) << 3);
                int colB = k0 + (((lane >> 3) & 1) << 3);
                uint32_t boff = (uint32_t)(rowB * BST + colB) * 2u;
                uint32_t bh0, bh1, bh2, bh3, bl0, bl1, bl2, bl3;
                ldm_x4(bh0, bh1, bh2, bh3, bHiS + boff);
                ldm_x4(bl0, bl1, bl2, bl3, bLoS + boff);
                mma_bf16(acc[0][pr * 2],     ah[0], bh0, bh1);
                mma_bf16(acc[1][pr * 2],     ah[1], bh0, bh1);
                mma_bf16(acc[0][pr * 2 + 1], ah[0], bh2, bh3);
                mma_bf16(acc[1][pr * 2 + 1], ah[1], bh2, bh3);
                mma_bf16(acc[0][pr * 2],     ah[0], bl0, bl1);
                mma_bf16(acc[1][pr * 2],     ah[1], bl0, bl1);
                mma_bf16(acc[0][pr * 2 + 1], ah[0], bl2, bl3);
                mma_bf16(acc[1][pr * 2 + 1], ah[1], bl2, bl3);
                mma_bf16(acc[0][pr * 2],     al[0], bh0, bh1);
                mma_bf16(acc[1][pr * 2],     al[1], bh0, bh1);
                mma_bf16(acc[0][pr * 2 + 1], al[0], bh2, bh3);
                mma_bf16(acc[1][pr * 2 + 1], al[1], bh2, bh3);

                if (doNext && ks == 1) {
                    int a0 = (pr < 2) ? ((pr == 0) ? pA0.x : pA0.z)
                                      : ((pr == 2) ? pA1.x : pA1.z);
                    int a1 = (pr < 2) ? ((pr == 0) ? pA0.y : pA0.w)
                                      : ((pr == 2) ? pA1.y : pA1.w);
                    make_w_pair(s1v, a0, a1,
                                s2S[jn + jg + 2 * pr], s2S[jn + jg + 2 * pr + 1],
                                lsum, hw[pr], lw[pr]);
                }
            }
        }

        if (doNext) {
            uint32_t off = (uint32_t)(ig * AST + jg) * 2u;
            asm volatile("st.shared.v4.b32 [%0], {%1,%2,%3,%4};"
                         :: "r"(sbN + off), "r"(hw[0]), "r"(hw[1]), "r"(hw[2]), "r"(hw[3]));
            asm volatile("st.shared.v4.b32 [%0], {%1,%2,%3,%4};"
                         :: "r"(sbN + A_BYTES + off), "r"(lw[0]), "r"(lw[1]), "r"(lw[2]), "r"(lw[3]));
            CP_WAIT0();
        }
        __syncthreads();
    }

    rsS[ig][t & 3] = lsum;
    __syncthreads();
    if (t < 128) rInv[t] = 1.f / (rsS[t][0] + rsS[t][1] + rsS[t][2] + rsS[t][3]);
    __syncthreads();

    const int g  = lane >> 2;
    const int tq = lane & 3;
#pragma unroll
    for (int mt = 0; mt < 2; ++mt) {
        int r0l = wm * 32 + mt * 16 + g;
        int r1l = r0l + 8;
        float inv0 = rInv[r0l], inv1 = rInv[r1l];
        size_t o0 = ((size_t)(b * N_ + i0 + r0l)) * F_;
        size_t o1 = ((size_t)(b * N_ + i0 + r1l)) * F_;
#pragma unroll
        for (int nt = 0; nt < 8; ++nt) {
            int col = wn * 64 + nt * 8 + 2 * tq;
            float x0 = acc[mt][nt][0] * inv0;
            float x1 = acc[mt][nt][1] * inv0;
            float x2 = acc[mt][nt][2] * inv1;
            float x3 = acc[mt][nt][3] * inv1;
            x0 = (x0 > 0.f) ? x0 : expm1f(x0);
            x1 = (x1 > 0.f) ? x1 : expm1f(x1);
            x2 = (x2 > 0.f) ? x2 : expm1f(x2);
            x3 = (x3 > 0.f) ? x3 : expm1f(x3);
            *(float2*)(out + o0 + col) = make_float2(x0, x1);
            *(float2*)(out + o1 + col) = make_float2(x2, x3);
        }
    }
}

// ---------------------------------------------------------------------------
extern "C" void kernel_launch(void* const* d_in, const int* in_sizes, int n_in,
                              void* d_out, int out_size)
{
    const float* h   = (const float*)d_in[0];
    const int*   adj = (const int*)  d_in[1];
    const float* Ww  = (const float*)d_in[2];
    const float* Wb  = (const float*)d_in[3];
    const float* aiw = (const float*)d_in[4];
    const float* aib = (const float*)d_in[5];
    const float* ajw = (const float*)d_in[6];
    const float* ajb = (const float*)d_in[7];
    float* out = (float*)d_out;

    static bool attrDone = false;
    if (!attrDone) {
        cudaFuncSetAttribute(k1_hmma, cudaFuncAttributeMaxDynamicSharedMemorySize,
                             DYN_SMEM);
        cudaFuncSetAttribute(k2_attn, cudaFuncAttributeMaxDynamicSharedMemorySize,
                             DYN_SMEM);
        attrDone = true;
    }

    k0_convW<<<128, 256>>>(Ww);
    k1_hmma<<<(B_ * N_) / 128, 512, DYN_SMEM>>>(h, Wb, aiw, aib, ajw, ajb);
    k2_attn<<<B_ * (N_ / 128), 512, DYN_SMEM>>>(adj, out);
}

// round 17
// speedup vs baseline: 1.1345x; 1.0092x over previous
#include <cuda_runtime.h>
#include <cuda_bf16.h>
#include <math.h>
#include <cstdint>
#include <cstddef>

#define B_   8
#define N_   2048
#define F_   256
#define ALPHA 0.2f

// ---------------- device scratch (allocation-free rule) ----------------
__device__ float g_s1[B_ * N_];
__device__ float g_s2[B_ * N_];
__device__ __nv_bfloat16 g_WhT_hi[B_ * F_ * N_];   // [b][f][j]
__device__ __nv_bfloat16 g_WhT_lo[B_ * F_ * N_];

__device__ __forceinline__ uint32_t smem_u32(const void* p) {
    uint32_t a;
    asm("{ .reg .u64 t; cvta.to.shared.u64 t, %1; cvt.u32.u64 %0, t; }"
        : "=r"(a) : "l"(p));
    return a;
}
__device__ __forceinline__ void ldm_x4(uint32_t& r0, uint32_t& r1,
                                       uint32_t& r2, uint32_t& r3, uint32_t addr) {
    asm volatile("ldmatrix.sync.aligned.m8n8.x4.shared.b16 {%0,%1,%2,%3}, [%4];"
                 : "=r"(r0), "=r"(r1), "=r"(r2), "=r"(r3) : "r"(addr));
}
__device__ __forceinline__ void mma_bf16(float* d, const uint32_t* a,
                                         uint32_t b0, uint32_t b1) {
    asm volatile(
        "mma.sync.aligned.m16n8k16.row.col.f32.bf16.bf16.f32 "
        "{%0,%1,%2,%3}, {%4,%5,%6,%7}, {%8,%9}, {%0,%1,%2,%3};"
        : "+f"(d[0]), "+f"(d[1]), "+f"(d[2]), "+f"(d[3])
        : "r"(a[0]), "r"(a[1]), "r"(a[2]), "r"(a[3]), "r"(b0), "r"(b1));
}
__device__ __forceinline__ void cp_async16(uint32_t dst, const void* src) {
    asm volatile("cp.async.cg.shared.global [%0], [%1], 16;"
                 :: "r"(dst), "l"(src) : "memory");
}
#define CP_COMMIT() asm volatile("cp.async.commit_group;" ::: "memory")
#define CP_WAIT0()  asm volatile("cp.async.wait_group 0;" ::: "memory")

__device__ __forceinline__ void split_pair(float v0, float v1,
                                           uint32_t& hiP, uint32_t& loP) {
    __nv_bfloat16 h0 = __float2bfloat16(v0), h1 = __float2bfloat16(v1);
    float r0 = v0 - __bfloat162float(h0);
    float r1 = v1 - __bfloat162float(h1);
    __nv_bfloat16 l0 = __float2bfloat16(r0), l1 = __float2bfloat16(r1);
    __nv_bfloat162 hp = __halves2bfloat162(h0, h1);
    __nv_bfloat162 lp = __halves2bfloat162(l0, l1);
    hiP = *(uint32_t*)&hp;
    loP = *(uint32_t*)&lp;
}

// w-pair: leaky+exp+mask, bf16 hi/lo split, rowsum accumulate
__device__ __forceinline__ void make_w_pair(float s1v, int a0, int a1,
                                            float s20, float s21,
                                            float& lsum, uint32_t& hiP, uint32_t& loP)
{
    float x0 = s1v + s20; x0 = fmaxf(x0, ALPHA * x0);
    float x1 = s1v + s21; x1 = fmaxf(x1, ALPHA * x1);
    float w0 = (a0 > 0) ? __expf(x0) : 0.f;
    float w1 = (a1 > 0) ? __expf(x1) : 0.f;
    lsum += w0 + w1;
    split_pair(w0, w1, hiP, loP);
}

// ---------------------------------------------------------------------------
// Shared tile constants (k1_hmma and k2 use the same skeleton)
// ---------------------------------------------------------------------------
#define KC2   32
#define AST   40
#define BST   40
#define A_BYTES (128 * AST * 2)           // 10240
#define B_BYTES (256 * BST * 2)           // 20480
#define STAGE   (2 * A_BYTES + 2 * B_BYTES)   // 61440
#define DYN_SMEM (2 * STAGE)                  // 122880

// ---------------------------------------------------------------------------
// Kernel 1: HMMA Wh = h @ W^T (+bias, s1/s2), bf16 3-term split.
//   CTA 128 rows x 256 out, 512 thr, 8 k-chunks of 32.
//   BOTH operands register-direct: h AND W loaded fp32 via LDG at segment
//   start (fly under MMAs), split in registers, stored at segment end.
//   No k0 launch, no cp.async staging. FUSED WhT transpose epilogue.
// ---------------------------------------------------------------------------
__global__ void __launch_bounds__(512, 1) k1_hmma(
    const float* __restrict__ h,  const float* __restrict__ Ww,
    const float* __restrict__ Wb, const float* __restrict__ aiw,
    const float* __restrict__ aib, const float* __restrict__ ajw,
    const float* __restrict__ ajb)
{
    extern __shared__ __align__(16) char smRaw[];
    __shared__ float sWb[F_], sAi[F_], sAj[F_];
    __shared__ float red1[128][4], red2[128][4];

    const int t    = threadIdx.x;
    const int lane = t & 31;
    const int wid  = t >> 5;
    const int wm   = wid & 3;
    const int wn   = wid >> 2;
    const int row0 = blockIdx.x * 128;

    const uint32_t smBase = smem_u32(smRaw);

    if (t < F_) { sWb[t] = Wb[t]; sAi[t] = aiw[t]; sAj[t] = ajw[t]; }

    // ---- roles ----
    const int ig = t >> 2;                   // A row 0..127
    const int jg = (t & 3) * 8;              // 8-k subgroup
    const int fB = t >> 1;                   // B row (out) 0..255
    const int hB = (t & 1) * 16;             // 16-k half

    const float* hP = h + (size_t)(row0 + ig) * F_;
    const float* wP = Ww + (size_t)fB * F_ + hB;

    float acc[2][8][4];
#pragma unroll
    for (int m = 0; m < 2; m++)
#pragma unroll
        for (int n = 0; n < 8; n++)
#pragma unroll
            for (int q = 0; q < 4; q++) acc[m][n][q] = 0.f;

    uint32_t hw[4], lw[4];
    const uint32_t aOff = (uint32_t)(ig * AST + jg) * 2u;
    const uint32_t bOff = (uint32_t)(fB * BST + hB) * 2u;

    // helper lambda-free B store: split 16 fp32 -> hi/lo, 4 v4 stores
#define K1_STORE_B(stBase, q0, q1, q2, q3)                                      \
    {                                                                           \
        uint32_t wh[8], wl[8];                                                  \
        split_pair((q0).x, (q0).y, wh[0], wl[0]);                               \
        split_pair((q0).z, (q0).w, wh[1], wl[1]);                               \
        split_pair((q1).x, (q1).y, wh[2], wl[2]);                               \
        split_pair((q1).z, (q1).w, wh[3], wl[3]);                               \
        split_pair((q2).x, (q2).y, wh[4], wl[4]);                               \
        split_pair((q2).z, (q2).w, wh[5], wl[5]);                               \
        split_pair((q3).x, (q3).y, wh[6], wl[6]);                               \
        split_pair((q3).z, (q3).w, wh[7], wl[7]);                               \
        uint32_t bHi = (stBase) + 2 * A_BYTES + bOff;                           \
        uint32_t bLo = bHi + B_BYTES;                                           \
        asm volatile("st.shared.v4.b32 [%0], {%1,%2,%3,%4};"                    \
                     :: "r"(bHi),      "r"(wh[0]), "r"(wh[1]), "r"(wh[2]), "r"(wh[3])); \
        asm volatile("st.shared.v4.b32 [%0], {%1,%2,%3,%4};"                    \
                     :: "r"(bHi + 16), "r"(wh[4]), "r"(wh[5]), "r"(wh[6]), "r"(wh[7])); \
        asm volatile("st.shared.v4.b32 [%0], {%1,%2,%3,%4};"                    \
                     :: "r"(bLo),      "r"(wl[0]), "r"(wl[1]), "r"(wl[2]), "r"(wl[3])); \
        asm volatile("st.shared.v4.b32 [%0], {%1,%2,%3,%4};"                    \
                     :: "r"(bLo + 16), "r"(wl[4]), "r"(wl[5]), "r"(wl[6]), "r"(wl[7])); \
    }

    // ---- prologue: chunk 0 for A and B, register-direct ----
    {
        float4 v0 = *(const float4*)(hP + jg);
        float4 v1 = *(const float4*)(hP + jg + 4);
        split_pair(v0.x, v0.y, hw[0], lw[0]);
        split_pair(v0.z, v0.w, hw[1], lw[1]);
        split_pair(v1.x, v1.y, hw[2], lw[2]);
        split_pair(v1.z, v1.w, hw[3], lw[3]);
        asm volatile("st.shared.v4.b32 [%0], {%1,%2,%3,%4};"
                     :: "r"(smBase + aOff), "r"(hw[0]), "r"(hw[1]), "r"(hw[2]), "r"(hw[3]));
        asm volatile("st.shared.v4.b32 [%0], {%1,%2,%3,%4};"
                     :: "r"(smBase + A_BYTES + aOff), "r"(lw[0]), "r"(lw[1]), "r"(lw[2]), "r"(lw[3]));

        float4 q0 = *(const float4*)(wP);
        float4 q1 = *(const float4*)(wP + 4);
        float4 q2 = *(const float4*)(wP + 8);
        float4 q3 = *(const float4*)(wP + 12);
        K1_STORE_B(smBase, q0, q1, q2, q3);
    }
    __syncthreads();

    for (int c = 0; c < 8; ++c) {
        const uint32_t sb   = smBase + (c & 1) * STAGE;
        const uint32_t sbN  = smBase + ((c + 1) & 1) * STAGE;
        const uint32_t aHiS = sb;
        const uint32_t aLoS = sb + A_BYTES;
        const uint32_t bHiS = sb + 2 * A_BYTES;
        const uint32_t bLoS = bHiS + B_BYTES;
        const bool doNext = (c + 1 < 8);
        const int  kn = (c + 1) * KC2;

        // segment start: LDG next chunk's h and W (fly under MMAs)
        float4 ph0, ph1, pw0, pw1, pw2, pw3;
        if (doNext) {
            ph0 = *(const float4*)(hP + kn + jg);
            ph1 = *(const float4*)(hP + kn + jg + 4);
            pw0 = *(const float4*)(wP + kn);
            pw1 = *(const float4*)(wP + kn + 4);
            pw2 = *(const float4*)(wP + kn + 8);
            pw3 = *(const float4*)(wP + kn + 12);
        }

        // ---- MMA(c) ----
#pragma unroll
        for (int ks = 0; ks < 2; ++ks) {
            const int k0 = ks * 16;
            uint32_t ah[2][4], al[2][4];
#pragma unroll
            for (int mt = 0; mt < 2; ++mt) {
                int arow = wm * 32 + mt * 16 + (lane & 15);
                uint32_t aoff = (uint32_t)(arow * AST + k0 + ((lane >> 4) << 3)) * 2u;
                ldm_x4(ah[mt][0], ah[mt][1], ah[mt][2], ah[mt][3], aHiS + aoff);
                ldm_x4(al[mt][0], al[mt][1], al[mt][2], al[mt][3], aLoS + aoff);
            }
#pragma unroll
            for (int pr = 0; pr < 4; ++pr) {
                int n0   = wn * 64 + pr * 16;
                int rowB = n0 + (lane & 7) + ((lane >> 4) << 3);
                int colB = k0 + (((lane >> 3) & 1) << 3);
                uint32_t boff = (uint32_t)(rowB * BST + colB) * 2u;
                uint32_t bh0, bh1, bh2, bh3, bl0, bl1, bl2, bl3;
                ldm_x4(bh0, bh1, bh2, bh3, bHiS + boff);
                ldm_x4(bl0, bl1, bl2, bl3, bLoS + boff);
                mma_bf16(acc[0][pr * 2],     ah[0], bh0, bh1);
                mma_bf16(acc[1][pr * 2],     ah[1], bh0, bh1);
                mma_bf16(acc[0][pr * 2 + 1], ah[0], bh2, bh3);
                mma_bf16(acc[1][pr * 2 + 1], ah[1], bh2, bh3);
                mma_bf16(acc[0][pr * 2],     ah[0], bl0, bl1);
                mma_bf16(acc[1][pr * 2],     ah[1], bl0, bl1);
                mma_bf16(acc[0][pr * 2 + 1], ah[0], bl2, bl3);
                mma_bf16(acc[1][pr * 2 + 1], ah[1], bl2, bl3);
                mma_bf16(acc[0][pr * 2],     al[0], bh0, bh1);
                mma_bf16(acc[1][pr * 2],     al[1], bh0, bh1);
                mma_bf16(acc[0][pr * 2 + 1], al[0], bh2, bh3);
                mma_bf16(acc[1][pr * 2 + 1], al[1], bh2, bh3);
            }
        }

        // segment end: split + store next A and B from registers
        if (doNext) {
            split_pair(ph0.x, ph0.y, hw[0], lw[0]);
            split_pair(ph0.z, ph0.w, hw[1], lw[1]);
            split_pair(ph1.x, ph1.y, hw[2], lw[2]);
            split_pair(ph1.z, ph1.w, hw[3], lw[3]);
            asm volatile("st.shared.v4.b32 [%0], {%1,%2,%3,%4};"
                         :: "r"(sbN + aOff), "r"(hw[0]), "r"(hw[1]), "r"(hw[2]), "r"(hw[3]));
            asm volatile("st.shared.v4.b32 [%0], {%1,%2,%3,%4};"
                         :: "r"(sbN + A_BYTES + aOff), "r"(lw[0]), "r"(lw[1]), "r"(lw[2]), "r"(lw[3]));
            K1_STORE_B(sbN, pw0, pw1, pw2, pw3);
        }
        __syncthreads();
    }
#undef K1_STORE_B

    // ---- epilogue part 1: bias, s1/s2 reduction ----
    const int g  = lane >> 2;
    const int tq = lane & 3;
#pragma unroll
    for (int mt = 0; mt < 2; ++mt) {
        int r0l = wm * 32 + mt * 16 + g;
        int r1l = r0l + 8;
        float a1_0 = 0.f, a2_0 = 0.f, a1_1 = 0.f, a2_1 = 0.f;
#pragma unroll
        for (int nt = 0; nt < 8; ++nt) {
            int col = wn * 64 + nt * 8 + 2 * tq;
            float b0 = sWb[col], b1 = sWb[col + 1];
            float i0v = sAi[col], i1v = sAi[col + 1];
            float j0v = sAj[col], j1v = sAj[col + 1];
            acc[mt][nt][0] += b0; acc[mt][nt][1] += b1;
            acc[mt][nt][2] += b0; acc[mt][nt][3] += b1;
            a1_0 = fmaf(acc[mt][nt][0], i0v, fmaf(acc[mt][nt][1], i1v, a1_0));
            a2_0 = fmaf(acc[mt][nt][0], j0v, fmaf(acc[mt][nt][1], j1v, a2_0));
            a1_1 = fmaf(acc[mt][nt][2], i0v, fmaf(acc[mt][nt][3], i1v, a1_1));
            a2_1 = fmaf(acc[mt][nt][2], j0v, fmaf(acc[mt][nt][3], j1v, a2_1));
        }
#pragma unroll
        for (int off = 1; off <= 2; off <<= 1) {
            a1_0 += __shfl_xor_sync(0xffffffffu, a1_0, off);
            a2_0 += __shfl_xor_sync(0xffffffffu, a2_0, off);
            a1_1 += __shfl_xor_sync(0xffffffffu, a1_1, off);
            a2_1 += __shfl_xor_sync(0xffffffffu, a2_1, off);
        }
        if (tq == 0) {
            red1[r0l][wn] = a1_0; red2[r0l][wn] = a2_0;
            red1[r1l][wn] = a1_1; red2[r1l][wn] = a2_1;
        }
    }
    __syncthreads();
    if (t < 128) {
        g_s1[row0 + t] = red1[t][0] + red1[t][1] + red1[t][2] + red1[t][3] + aib[0];
        g_s2[row0 + t] = red2[t][0] + red2[t][1] + red2[t][2] + red2[t][3] + ajb[0];
    }

    // ---- epilogue part 2: FUSED transpose + bf16 split, two 128f passes ----
    float* ts = (float*)smRaw;
    const int b   = row0 >> 11;
    const int jlo = row0 & (N_ - 1);
    const int fLoc = t >> 2;                 // 0..127
    const int jseg = (t & 3) * 32;           // 0,32,64,96

#pragma unroll
    for (int fh = 0; fh < 2; ++fh) {
        __syncthreads();
        if ((wn >> 1) == fh) {
#pragma unroll
            for (int mt = 0; mt < 2; ++mt) {
                int r0l = wm * 32 + mt * 16 + g;
                int r1l = r0l + 8;
#pragma unroll
                for (int nt = 0; nt < 8; ++nt) {
                    int colL = (wn & 1) * 64 + nt * 8 + 2 * tq;
                    *(float2*)&ts[r0l * 132 + colL] =
                        make_float2(acc[mt][nt][0], acc[mt][nt][1]);
                    *(float2*)&ts[r1l * 132 + colL] =
                        make_float2(acc[mt][nt][2], acc[mt][nt][3]);
                }
            }
        }
        __syncthreads();
        uint32_t hp[16], lp[16];
#pragma unroll
        for (int e = 0; e < 32; e += 2) {
            float v0 = ts[(jseg + e) * 132 + fLoc];
            float v1 = ts[(jseg + e + 1) * 132 + fLoc];
            split_pair(v0, v1, hp[e >> 1], lp[e >> 1]);
        }
        size_t dst = ((size_t)(b * F_ + fh * 128 + fLoc)) * N_ + jlo + jseg;
        uint4* dh = (uint4*)(g_WhT_hi + dst);
        uint4* dl = (uint4*)(g_WhT_lo + dst);
        dh[0] = make_uint4(hp[0],  hp[1],  hp[2],  hp[3]);
        dh[1] = make_uint4(hp[4],  hp[5],  hp[6],  hp[7]);
        dh[2] = make_uint4(hp[8],  hp[9],  hp[10], hp[11]);
        dh[3] = make_uint4(hp[12], hp[13], hp[14], hp[15]);
        dl[0] = make_uint4(lp[0],  lp[1],  lp[2],  lp[3]);
        dl[1] = make_uint4(lp[4],  lp[5],  lp[6],  lp[7]);
        dl[2] = make_uint4(lp[8],  lp[9],  lp[10], lp[11]);
        dl[3] = make_uint4(lp[12], lp[13], lp[14], lp[15]);
    }
}

// ---------------------------------------------------------------------------
// Kernel 2: HMMA attention GEMM (proven best: 512 thr, 128i x 256f, KC=32)
// ---------------------------------------------------------------------------
#define NCH2  (N_ / KC2)                  // 64 chunks

__global__ void __launch_bounds__(512, 1) k2_attn(
    const int* __restrict__ adj, float* __restrict__ out)
{
    extern __shared__ __align__(16) char smRaw[];
    __shared__ float s1S[128];
    __shared__ __align__(16) float s2S[N_];
    __shared__ float rsS[128][4];
    __shared__ float rInv[128];

    const int t    = threadIdx.x;
    const int lane = t & 31;
    const int wid  = t >> 5;
    const int wm   = wid & 3;
    const int wn   = wid >> 2;
    const int b    = blockIdx.x >> 4;
    const int i0   = (blockIdx.x & 15) * 128;

    const uint32_t smBase = smem_u32(smRaw);

    if (t < 128) s1S[t] = g_s1[b * N_ + i0 + t];
    {
        const float4* s2g = (const float4*)(g_s2 + b * N_);
#pragma unroll
        for (int k = t; k < N_ / 4; k += 512) ((float4*)s2S)[k] = s2g[k];
    }

    const int ig = t >> 2;
    const int jg = (t & 3) * 8;
    const int fB = t >> 1;
    const int hB = (t & 1) * 16;

    const int* adjP = adj + (size_t)(b * N_ + i0 + ig) * N_;
    const __nv_bfloat16* bhP = g_WhT_hi + (size_t)(b * F_ + fB) * N_;
    const __nv_bfloat16* blP = g_WhT_lo + (size_t)(b * F_ + fB) * N_;

    float acc[2][8][4];
#pragma unroll
    for (int m = 0; m < 2; m++)
#pragma unroll
        for (int n = 0; n < 8; n++)
#pragma unroll
            for (int q = 0; q < 4; q++) acc[m][n][q] = 0.f;
    float lsum = 0.f;

    uint32_t hw[4], lw[4];

    __syncthreads();

    {
        int4 a0 = *(const int4*)(adjP + jg);
        int4 a1 = *(const int4*)(adjP + jg + 4);
        const float s1v = s1S[ig];
        make_w_pair(s1v, a0.x, a0.y, s2S[jg + 0], s2S[jg + 1], lsum, hw[0], lw[0]);
        make_w_pair(s1v, a0.z, a0.w, s2S[jg + 2], s2S[jg + 3], lsum, hw[1], lw[1]);
        make_w_pair(s1v, a1.x, a1.y, s2S[jg + 4], s2S[jg + 5], lsum, hw[2], lw[2]);
        make_w_pair(s1v, a1.z, a1.w, s2S[jg + 6], s2S[jg + 7], lsum, hw[3], lw[3]);

        uint32_t dH = smBase + 2 * A_BYTES + (uint32_t)(fB * BST + hB) * 2u;
        cp_async16(dH,      bhP + hB);
        cp_async16(dH + 16, bhP + hB + 8);
        cp_async16(dH + B_BYTES,      blP + hB);
        cp_async16(dH + B_BYTES + 16, blP + hB + 8);
        CP_COMMIT();

        uint32_t off = (uint32_t)(ig * AST + jg) * 2u;
        asm volatile("st.shared.v4.b32 [%0], {%1,%2,%3,%4};"
                     :: "r"(smBase + off), "r"(hw[0]), "r"(hw[1]), "r"(hw[2]), "r"(hw[3]));
        asm volatile("st.shared.v4.b32 [%0], {%1,%2,%3,%4};"
                     :: "r"(smBase + A_BYTES + off), "r"(lw[0]), "r"(lw[1]), "r"(lw[2]), "r"(lw[3]));
        CP_WAIT0();
    }
    __syncthreads();

    for (int c = 0; c < NCH2; ++c) {
        const uint32_t sb   = smBase + (c & 1) * STAGE;
        const uint32_t sbN  = smBase + ((c + 1) & 1) * STAGE;
        const uint32_t aHiS = sb;
        const uint32_t aLoS = sb + A_BYTES;
        const uint32_t bHiS = sb + 2 * A_BYTES;
        const uint32_t bLoS = bHiS + B_BYTES;
        const bool doNext = (c + 1 < NCH2);
        const int  jn = (c + 1) * KC2;

        int4 pA0, pA1;
        if (doNext) {
            uint32_t dH = sbN + 2 * A_BYTES + (uint32_t)(fB * BST + hB) * 2u;
            cp_async16(dH,      bhP + jn + hB);
            cp_async16(dH + 16, bhP + jn + hB + 8);
            cp_async16(dH + B_BYTES,      blP + jn + hB);
            cp_async16(dH + B_BYTES + 16, blP + jn + hB + 8);
            CP_COMMIT();
            pA0 = *(const int4*)(adjP + jn + jg);
            pA1 = *(const int4*)(adjP + jn + jg + 4);
        }
        const float s1v = s1S[ig];

#pragma unroll
        for (int ks = 0; ks < 2; ++ks) {
            const int k0 = ks * 16;
            uint32_t ah[2][4], al[2][4];
#pragma unroll
            for (int mt = 0; mt < 2; ++mt) {
                int arow = wm * 32 + mt * 16 + (lane & 15);
                uint32_t aoff = (uint32_t)(arow * AST + k0 + ((lane >> 4) << 3)) * 2u;
                ldm_x4(ah[mt][0], ah[mt][1], ah[mt][2], ah[mt][3], aHiS + aoff);
                ldm_x4(al[mt][0], al[mt][1], al[mt][2], al[mt][3], aLoS + aoff);
            }
#pragma unroll
            for (int pr = 0; pr < 4; ++pr) {
                int n0   = wn * 64 + pr * 16;
                int rowB = n0 + (lane & 7) + ((lane >> 4) << 3);
                int colB = k0 + (((lane >> 3) & 1) << 3);
                uint32_t boff = (uint32_t)(rowB * BST + colB) * 2u;
                uint32_t bh0, bh1, bh2, bh3, bl0, bl1, bl2, bl3;
                ldm_x4(bh0, bh1, bh2, bh3, bHiS + boff);
                ldm_x4(bl0, bl1, bl2, bl3, bLoS + boff);
                mma_bf16(acc[0][pr * 2],     ah[0], bh0, bh1);
                mma_bf16(acc[1][pr * 2],     ah[1], bh0, bh1);
                mma_bf16(acc[0][pr * 2 + 1], ah[0], bh2, bh3);
                mma_bf16(acc[1][pr * 2 + 1], ah[1], bh2, bh3);
                mma_bf16(acc[0][pr * 2],     ah[0], bl0, bl1);
                mma_bf16(acc[1][pr * 2],     ah[1], bl0, bl1);
                mma_bf16(acc[0][pr * 2 + 1], ah[0], bl2, bl3);
                mma_bf16(acc[1][pr * 2 + 1], ah[1], bl2, bl3);
                mma_bf16(acc[0][pr * 2],     al[0], bh0, bh1);
                mma_bf16(acc[1][pr * 2],     al[1], bh0, bh1);
                mma_bf16(acc[0][pr * 2 + 1], al[0], bh2, bh3);
                mma_bf16(acc[1][pr * 2 + 1], al[1], bh2, bh3);

                if (doNext && ks == 1) {
                    int a0 = (pr < 2) ? ((pr == 0) ? pA0.x : pA0.z)
                                      : ((pr == 2) ? pA1.x : pA1.z);
                    int a1 = (pr < 2) ? ((pr == 0) ? pA0.y : pA0.w)
                                      : ((pr == 2) ? pA1.y : pA1.w);
                    make_w_pair(s1v, a0, a1,
                                s2S[jn + jg + 2 * pr], s2S[jn + jg + 2 * pr + 1],
                                lsum, hw[pr], lw[pr]);
                }
            }
        }

        if (doNext) {
            uint32_t off = (uint32_t)(ig * AST + jg) * 2u;
            asm volatile("st.shared.v4.b32 [%0], {%1,%2,%3,%4};"
                         :: "r"(sbN + off), "r"(hw[0]), "r"(hw[1]), "r"(hw[2]), "r"(hw[3]));
            asm volatile("st.shared.v4.b32 [%0], {%1,%2,%3,%4};"
                         :: "r"(sbN + A_BYTES + off), "r"(lw[0]), "r"(lw[1]), "r"(lw[2]), "r"(lw[3]));
            CP_WAIT0();
        }
        __syncthreads();
    }

    rsS[ig][t & 3] = lsum;
    __syncthreads();
    if (t < 128) rInv[t] = 1.f / (rsS[t][0] + rsS[t][1] + rsS[t][2] + rsS[t][3]);
    __syncthreads();

    const int g  = lane >> 2;
    const int tq = lane & 3;
#pragma unroll
    for (int mt = 0; mt < 2; ++mt) {
        int r0l = wm * 32 + mt * 16 + g;
        int r1l = r0l + 8;
        float inv0 = rInv[r0l], inv1 = rInv[r1l];
        size_t o0 = ((size_t)(b * N_ + i0 + r0l)) * F_;
        size_t o1 = ((size_t)(b * N_ + i0 + r1l)) * F_;
#pragma unroll
        for (int nt = 0; nt < 8; ++nt) {
            int col = wn * 64 + nt * 8 + 2 * tq;
            float x0 = acc[mt][nt][0] * inv0;
            float x1 = acc[mt][nt][1] * inv0;
            float x2 = acc[mt][nt][2] * inv1;
            float x3 = acc[mt][nt][3] * inv1;
            x0 = (x0 > 0.f) ? x0 : expm1f(x0);
            x1 = (x1 > 0.f) ? x1 : expm1f(x1);
            x2 = (x2 > 0.f) ? x2 : expm1f(x2);
            x3 = (x3 > 0.f) ? x3 : expm1f(x3);
            *(float2*)(out + o0 + col) = make_float2(x0, x1);
            *(float2*)(out + o1 + col) = make_float2(x2, x3);
        }
    }
}

// ---------------------------------------------------------------------------
extern "C" void kernel_launch(void* const* d_in, const int* in_sizes, int n_in,
                              void* d_out, int out_size)
{
    const float* h   = (const float*)d_in[0];
    const int*   adj = (const int*)  d_in[1];
    const float* Ww  = (const float*)d_in[2];
    const float* Wb  = (const float*)d_in[3];
    const float* aiw = (const float*)d_in[4];
    const float* aib = (const float*)d_in[5];
    const float* ajw = (const float*)d_in[6];
    const float* ajb = (const float*)d_in[7];
    float* out = (float*)d_out;

    static bool attrDone = false;
    if (!attrDone) {
        cudaFuncSetAttribute(k1_hmma, cudaFuncAttributeMaxDynamicSharedMemorySize,
                             DYN_SMEM);
        cudaFuncSetAttribute(k2_attn, cudaFuncAttributeMaxDynamicSharedMemorySize,
                             DYN_SMEM);
        attrDone = true;
    }

    k1_hmma<<<(B_ * N_) / 128, 512, DYN_SMEM>>>(h, Ww, Wb, aiw, aib, ajw, ajb);
    k2_attn<<<B_ * (N_ / 128), 512, DYN_SMEM>>>(adj, out);
}